// round 14
// baseline (speedup 1.0000x reference)
#include <cuda_runtime.h>
#include <cuda_fp16.h>
#include <math.h>
#include <stdint.h>

#define BB 8
#define SQL 1024
#define SKL 1024
#define DM  1024
#define NH  16
#define DH  64

// ---------------- scratch (static device arrays; no cudaMalloc) -------------
__device__ float g_v   [BB*SKL*DM];
__device__ float g_s   [(long)BB*SQL*SKL];
__device__ float g_newq[BB*SQL*DM];
__device__ float g_newk[BB*SKL*DM];

__device__ __half g_hsh [8192L*1024];
__device__ __half g_ctxh[8192L*1024];
__device__ __half g_qh  [8192L*1024];
__device__ __half g_kh  [8192L*1024];
__device__ __half g_vTh [8192L*1024];
__device__ __half g_ph  [8192L*1024];
__device__ __half g_gh  [8192L*1024];
__device__ __half g_Wqh [1024L*1024];
__device__ __half g_Wkh [1024L*1024];
__device__ __half g_Wvh [1024L*1024];
__device__ __half g_Woh [1024L*1024];
__device__ __half g_Wmh [1024L*1024];
// LayerNorm outputs for MHA
__device__ __half g_mqh[8192L*1024];
__device__ __half g_mql[8192L*1024];
__device__ __half g_mkh[8192L*1024];

// ---------------- helpers ----------------------------------------------------
__device__ __forceinline__ uint32_t smem_u32(const void* p) {
    uint32_t a;
    asm("{ .reg .u64 t; cvta.to.shared.u64 t, %1; cvt.u32.u64 %0, t; }"
        : "=r"(a) : "l"(p));
    return a;
}
#define CP_ASYNC16(sa, ga) \
    asm volatile("cp.async.cg.shared.global [%0], [%1], 16;" :: "r"(sa), "l"(ga))
#define CP_COMMIT() asm volatile("cp.async.commit_group;" ::: "memory")
#define CP_WAIT1()  asm volatile("cp.async.wait_group 1;" ::: "memory")
#define CP_WAIT2()  asm volatile("cp.async.wait_group 2;" ::: "memory")

#define LDSM_X4(r0, r1, r2, r3, a) \
    asm volatile("ldmatrix.sync.aligned.m8n8.x4.shared.b16 {%0,%1,%2,%3}, [%4];" \
        : "=r"(r0), "=r"(r1), "=r"(r2), "=r"(r3) : "r"(a))

#define MMA16816(c, a, b) \
    asm volatile("mma.sync.aligned.m16n8k16.row.col.f32.f16.f16.f32 " \
        "{%0,%1,%2,%3}, {%4,%5,%6,%7}, {%8,%9}, {%0,%1,%2,%3};" \
        : "+f"((c)[0]), "+f"((c)[1]), "+f"((c)[2]), "+f"((c)[3]) \
        : "r"((a)[0]), "r"((a)[1]), "r"((a)[2]), "r"((a)[3]), \
          "r"((b)[0]), "r"((b)[1]))

__device__ __forceinline__ uint32_t pack_h2(__half a, __half b) {
    __half2 t = __halves2half2(a, b);
    return *(uint32_t*)&t;
}

// ---------------- HMMA GEMM: 128x128 tile, K=1024, 4-stage, 2 CTA/SM ---------
// A [M, 1024] fp16 K-major, B [N_, 1024] fp16 K-major.
// Template-specialized output: CFMODE -> f32 C, else fp16 C. HASBIAS optional.
#define STAGES 4
#define STAGE_BYTES 16384
#define GEMM_SMEM (STAGES * STAGE_BYTES)   // 65536
#define KK 1024

template<bool CFMODE, bool HASBIAS>
__global__ void __launch_bounds__(256, 2) mma_gemm(
    const __half* __restrict__ A, const __half* __restrict__ B,
    const float* __restrict__ bias,
    float* __restrict__ Cf, __half* __restrict__ Ch,
    int N, float alpha, long sA, long sB, long sCf, long sCh)
{
    extern __shared__ char smem[];
    const uint32_t sbase = smem_u32(smem);
    const int tid = threadIdx.x, warp = tid >> 5, lane = tid & 31;
    const int wM = warp >> 1, wN = warp & 1;
    const long bm = (long)blockIdx.y * 128, bn = (long)blockIdx.x * 128;
    const int z = blockIdx.z;

    const int lrow = tid >> 1;
    const int lc0 = (tid & 1) * 2;
    const __half* Ag = A + z * sA + (bm + lrow) * (long)KK + lc0 * 8;
    const __half* Bg = B + z * sB + (bn + lrow) * (long)KK + lc0 * 8;
    const uint32_t sw = (uint32_t)((lrow >> 1) & 3);
    const uint32_t soff0 = (uint32_t)lrow * 64 + (((uint32_t)lc0     ^ sw) << 4);
    const uint32_t soff1 = (uint32_t)lrow * 64 + (((uint32_t)(lc0+1) ^ sw) << 4);

    float acc[2][8][4];
    #pragma unroll
    for (int i = 0; i < 2; ++i)
        #pragma unroll
        for (int j = 0; j < 8; ++j)
            #pragma unroll
            for (int k = 0; k < 4; ++k) acc[i][j][k] = 0.f;

    const int NCH = KK / 32;   // 32

    #pragma unroll
    for (int s = 0; s < STAGES - 1; ++s) {
        const uint32_t st = sbase + s * STAGE_BYTES;
        CP_ASYNC16(st + soff0,        Ag + (long)s * 32);
        CP_ASYNC16(st + soff1,        Ag + (long)s * 32 + 8);
        CP_ASYNC16(st + 8192 + soff0, Bg + (long)s * 32);
        CP_ASYNC16(st + 8192 + soff1, Bg + (long)s * 32 + 8);
        CP_COMMIT();
    }

    const int l15 = lane & 15;
    const int lk  = lane >> 4;

    #pragma unroll 2
    for (int c = 0; c < NCH; ++c) {
        CP_WAIT2();
        __syncthreads();

        const int nc = c + STAGES - 1;
        if (nc < NCH) {
            const uint32_t st = sbase + (nc % STAGES) * STAGE_BYTES;
            CP_ASYNC16(st + soff0,        Ag + (long)nc * 32);
            CP_ASYNC16(st + soff1,        Ag + (long)nc * 32 + 8);
            CP_ASYNC16(st + 8192 + soff0, Bg + (long)nc * 32);
            CP_ASYNC16(st + 8192 + soff1, Bg + (long)nc * 32 + 8);
        }
        CP_COMMIT();

        const uint32_t aB = sbase + (c % STAGES) * STAGE_BYTES;
        const uint32_t bB = aB + 8192;
        #pragma unroll
        for (int ks = 0; ks < 2; ++ks) {
            uint32_t a[2][4], b[8][2];
            #pragma unroll
            for (int mt = 0; mt < 2; ++mt) {
                const int row = wM * 32 + mt * 16 + l15;
                const uint32_t kc = (uint32_t)(ks * 2 + lk);
                const uint32_t ad = aB + row * 64 + ((kc ^ ((row >> 1) & 3)) << 4);
                LDSM_X4(a[mt][0], a[mt][1], a[mt][2], a[mt][3], ad);
            }
            #pragma unroll
            for (int p = 0; p < 4; ++p) {
                const int row = wN * 64 + p * 16 + l15;
                const uint32_t kc = (uint32_t)(ks * 2 + lk);
                const uint32_t bd = bB + row * 64 + ((kc ^ ((row >> 1) & 3)) << 4);
                uint32_t r0, r1, r2, r3;
                LDSM_X4(r0, r1, r2, r3, bd);
                b[2 * p][0] = r0; b[2 * p][1] = r2;
                b[2 * p + 1][0] = r1; b[2 * p + 1][1] = r3;
            }
            #pragma unroll
            for (int mt = 0; mt < 2; ++mt)
                #pragma unroll
                for (int nt = 0; nt < 8; ++nt)
                    MMA16816(acc[mt][nt], a[mt], b[nt]);
        }
    }

    const int g = lane >> 2, t2 = 2 * (lane & 3);
    #pragma unroll
    for (int mt = 0; mt < 2; ++mt) {
        const long r0 = bm + wM * 32 + mt * 16 + g;
        const long r1 = r0 + 8;
        #pragma unroll
        for (int nt = 0; nt < 8; ++nt) {
            const int gcol = (int)bn + wN * 64 + nt * 8 + t2;
            float v00 = acc[mt][nt][0] * alpha, v01 = acc[mt][nt][1] * alpha;
            float v10 = acc[mt][nt][2] * alpha, v11 = acc[mt][nt][3] * alpha;
            if (HASBIAS) {
                const float2 bb = *(const float2*)(bias + gcol);
                v00 += bb.x; v01 += bb.y; v10 += bb.x; v11 += bb.y;
            }
            if (CFMODE) {
                float2 o0; o0.x = v00; o0.y = v01;
                float2 o1; o1.x = v10; o1.y = v11;
                *(float2*)(Cf + z * sCf + r0 * (long)N + gcol) = o0;
                *(float2*)(Cf + z * sCf + r1 * (long)N + gcol) = o1;
            } else {
                *(__half2*)(Ch + z * sCh + r0 * (long)N + gcol) =
                    __halves2half2(__float2half(v00), __float2half(v01));
                *(__half2*)(Ch + z * sCh + r1 * (long)N + gcol) =
                    __halves2half2(__float2half(v10), __float2half(v11));
            }
        }
    }
}

// ---------------- f32 -> fp16 dense conversion -------------------------------
__global__ void __launch_bounds__(256) convert_h(
    const float* __restrict__ in, __half* __restrict__ out, long totalPairs)
{
    for (long p = blockIdx.x * (long)blockDim.x + threadIdx.x; p < totalPairs;
         p += (long)gridDim.x * blockDim.x) {
        float2 x = ((const float2*)in)[p];
        ((__half2*)out)[p] = __halves2half2(__float2half(x.x), __float2half(x.y));
    }
}

// ---------------- merged f32 -> fp16 conversion for the 5 weights ------------
#define WSEG 524288L
struct CvtW {
    const float *s0, *s1, *s2, *s3, *s4;
    __half *d0, *d1, *d2, *d3, *d4;
};
__global__ void __launch_bounds__(256) convert_w5(CvtW a)
{
    const long total = 5 * WSEG;
    for (long p = blockIdx.x * (long)blockDim.x + threadIdx.x; p < total;
         p += (long)gridDim.x * blockDim.x) {
        const int w = (int)(p >> 19);
        const long off = p & (WSEG - 1);
        const float* src = (w == 0) ? a.s0 : (w == 1) ? a.s1 : (w == 2) ? a.s2
                         : (w == 3) ? a.s3 : a.s4;
        __half* dst = (w == 0) ? a.d0 : (w == 1) ? a.d1 : (w == 2) ? a.d2
                    : (w == 3) ? a.d3 : a.d4;
        float2 x = ((const float2*)src)[off];
        ((__half2*)dst)[off] = __halves2half2(__float2half(x.x), __float2half(x.y));
    }
}

// ---------------- v [B,SK,D] f32 -> vT fp16 [B, D, SK] -----------------------
__global__ void __launch_bounds__(256) transconv_v(
    const float* __restrict__ v, __half* __restrict__ out)
{
    __shared__ float t[32][33];
    const int d0 = blockIdx.x * 32, s0 = blockIdx.y * 32, b = blockIdx.z;
    const int tx = threadIdx.x & 31, ty = threadIdx.x >> 5;
    #pragma unroll
    for (int i = 0; i < 32; i += 8)
        t[ty + i][tx] = v[((long)b * SKL + s0 + ty + i) * DM + d0 + tx];
    __syncthreads();
    #pragma unroll
    for (int i = 0; i < 32; i += 8) {
        const int d = d0 + ty + i, s = s0 + tx;
        out[((long)b * DM + d) * (long)SKL + s] = __float2half(t[tx][ty + i]);
    }
}

// ---------------- block reductions -------------------------------------------
__device__ __forceinline__ float block_reduce_max(float v) {
    __shared__ float sh[8];
    int lane = threadIdx.x & 31, wid = threadIdx.x >> 5;
    #pragma unroll
    for (int o = 16; o; o >>= 1) v = fmaxf(v, __shfl_xor_sync(0xffffffffu, v, o));
    if (lane == 0) sh[wid] = v;
    __syncthreads();
    if (threadIdx.x == 0) {
        float r = sh[0];
        #pragma unroll
        for (int i = 1; i < 8; ++i) r = fmaxf(r, sh[i]);
        sh[0] = r;
    }
    __syncthreads();
    float r = sh[0];
    __syncthreads();
    return r;
}
__device__ __forceinline__ float block_reduce_sum(float v) {
    __shared__ float sh[8];
    int lane = threadIdx.x & 31, wid = threadIdx.x >> 5;
    #pragma unroll
    for (int o = 16; o; o >>= 1) v += __shfl_xor_sync(0xffffffffu, v, o);
    if (lane == 0) sh[wid] = v;
    __syncthreads();
    if (threadIdx.x == 0) {
        float r = sh[0];
        #pragma unroll
        for (int i = 1; i < 8; ++i) r += sh[i];
        sh[0] = r;
    }
    __syncthreads();
    float r = sh[0];
    __syncthreads();
    return r;
}

// ---------------- guide softmax -> fp16 dense (1-pass) -----------------------
__global__ void __launch_bounds__(256) softmax_h(
    const float* __restrict__ x, __half* __restrict__ outh)
{
    x += (long)blockIdx.x * SKL;
    __half2* row = (__half2*)(outh + (long)blockIdx.x * SKL);
    const int tid = threadIdx.x;
    const float4 xv = *(const float4*)(x + tid * 4);
    float lm = fmaxf(fmaxf(xv.x, xv.y), fmaxf(xv.z, xv.w));
    const float m = block_reduce_max(lm);
    float e0 = __expf(xv.x - m), e1 = __expf(xv.y - m);
    float e2 = __expf(xv.z - m), e3 = __expf(xv.w - m);
    const float s = block_reduce_sum(e0 + e1 + e2 + e3);
    const float inv = 1.f / s;
    row[tid * 2]     = __halves2half2(__float2half(e0 * inv), __float2half(e1 * inv));
    row[tid * 2 + 1] = __halves2half2(__float2half(e2 * inv), __float2half(e3 * inv));
}

// ---------------- fused ReLU + LayerNorm -> fp16 hi (+ optional lo) ----------
__global__ void __launch_bounds__(256) relu_ln_split(
    const float* __restrict__ x, const float* __restrict__ g,
    const float* __restrict__ bparm,
    __half* __restrict__ oh, __half* __restrict__ ol)
{
    x  += (long)blockIdx.x * DM;
    oh += (long)blockIdx.x * DM;
    const int tid = threadIdx.x;
    float4 xv = *(const float4*)(x + tid * 4);
    xv.x = fmaxf(xv.x, 0.f); xv.y = fmaxf(xv.y, 0.f);
    xv.z = fmaxf(xv.z, 0.f); xv.w = fmaxf(xv.w, 0.f);
    const float s1 = block_reduce_sum(xv.x + xv.y + xv.z + xv.w);
    const float s2 = block_reduce_sum(xv.x * xv.x + xv.y * xv.y +
                                      xv.z * xv.z + xv.w * xv.w);
    const float mean = s1 / DM;
    const float var  = s2 / DM - mean * mean;
    const float inv  = rsqrtf(var + 1e-5f);
    const float4 gv = *(const float4*)(g + tid * 4);
    const float4 bv = *(const float4*)(bparm + tid * 4);
    float y0 = (xv.x - mean) * inv * gv.x + bv.x;
    float y1 = (xv.y - mean) * inv * gv.y + bv.y;
    float y2 = (xv.z - mean) * inv * gv.z + bv.z;
    float y3 = (xv.w - mean) * inv * gv.w + bv.w;
    __half h0 = __float2half(y0), h1 = __float2half(y1);
    __half h2 = __float2half(y2), h3 = __float2half(y3);
    *(__half2*)(oh + tid * 4)     = __halves2half2(h0, h1);
    *(__half2*)(oh + tid * 4 + 2) = __halves2half2(h2, h3);
    if (ol) {
        ol += (long)blockIdx.x * DM;
        *(__half2*)(ol + tid * 4)     = __halves2half2(
            __float2half(y0 - __half2float(h0)),
            __float2half(y1 - __half2float(h1)));
        *(__half2*)(ol + tid * 4 + 2) = __halves2half2(
            __float2half(y2 - __half2float(h2)),
            __float2half(y3 - __half2float(h3)));
    }
}

// ---------------- tensor-core flash MHA --------------------------------------
// S = QK^T 2-term (Qh,Ql x Kh); PV 1-term (Ph x Vh).
#define MHA_STAGE 16384
#define MHA_SMEM (32768 + 2 * MHA_STAGE)   // 65536
__global__ void __launch_bounds__(256, 1) mha_mma_kernel(
    const __half* __restrict__ qh, const __half* __restrict__ ql,
    const __half* __restrict__ kh,
    const __half* __restrict__ vTh, float* __restrict__ out)
{
    extern __shared__ char smem[];
    const uint32_t sb = smem_u32(smem);
    const uint32_t sQh = sb, sQl = sb + 16384;
    const int tid = threadIdx.x, warp = tid >> 5, lane = tid & 31;
    const int bh = blockIdx.y, b = bh >> 4, h = bh & 15;
    const int q0 = blockIdx.x * 128;

    #pragma unroll
    for (int j = 0; j < 4; ++j) {
        const int idx = tid + j * 256;
        const int r = idx >> 3, c = idx & 7;
        const uint32_t soff = (uint32_t)r * 128 + ((uint32_t)(c ^ (r & 7)) << 4);
        const long gg = ((long)(b * SQL + q0 + r)) * DM + h * DH + c * 8;
        CP_ASYNC16(sQh + soff, qh + gg);
        CP_ASYNC16(sQl + soff, ql + gg);
    }
    auto issue_tile = [&](int t) {
        const uint32_t bufb = sb + 32768 + (uint32_t)(t & 1) * MHA_STAGE;
        #pragma unroll
        for (int j = 0; j < 2; ++j) {
            const int idx = tid + j * 256;
            const int r = idx >> 3, c = idx & 7;
            const uint32_t soff = (uint32_t)r * 128 + ((uint32_t)(c ^ (r & 7)) << 4);
            const long gk = ((long)(b * SKL + t * 64 + r)) * DM + h * DH + c * 8;
            CP_ASYNC16(bufb + soff, kh + gk);
            const long gv = ((long)(b * DM + h * DH + r)) * (long)SKL + t * 64 + c * 8;
            CP_ASYNC16(bufb + 8192 + soff, vTh + gv);
        }
    };
    issue_tile(0);
    CP_COMMIT();

    float oacc[8][4];
    #pragma unroll
    for (int i = 0; i < 8; ++i)
        #pragma unroll
        for (int j = 0; j < 4; ++j) oacc[i][j] = 0.f;
    float mrow[2] = {-1e30f, -1e30f}, lrow[2] = {0.f, 0.f};

    const int l15 = lane & 15, lk = lane >> 4;

    for (int t = 0; t < 16; ++t) {
        if (t + 1 < 16) issue_tile(t + 1);
        CP_COMMIT();
        CP_WAIT1();
        __syncthreads();
        const uint32_t bufb = sb + 32768 + (uint32_t)(t & 1) * MHA_STAGE;

        float sc[8][4];
        #pragma unroll
        for (int i = 0; i < 8; ++i)
            #pragma unroll
            for (int j = 0; j < 4; ++j) sc[i][j] = 0.f;

        #pragma unroll
        for (int ks = 0; ks < 4; ++ks) {
            const int arow = warp * 16 + l15;
            const uint32_t ac = ((uint32_t)((ks * 2 + lk) ^ (arow & 7)) << 4)
                              + (uint32_t)arow * 128;
            uint32_t aH[4], aL[4];
            LDSM_X4(aH[0], aH[1], aH[2], aH[3], sQh + ac);
            LDSM_X4(aL[0], aL[1], aL[2], aL[3], sQl + ac);
            uint32_t bH[8][2];
            #pragma unroll
            for (int p = 0; p < 4; ++p) {
                const int br = p * 16 + l15;
                const uint32_t bc = ((uint32_t)((ks * 2 + lk) ^ (br & 7)) << 4)
                                  + (uint32_t)br * 128;
                uint32_t r0, r1, r2, r3;
                LDSM_X4(r0, r1, r2, r3, bufb + bc);
                bH[2*p][0] = r0; bH[2*p][1] = r2;
                bH[2*p+1][0] = r1; bH[2*p+1][1] = r3;
            }
            #pragma unroll
            for (int nt = 0; nt < 8; ++nt) {
                MMA16816(sc[nt], aH, bH[nt]);
                MMA16816(sc[nt], aL, bH[nt]);
            }
        }

        float mx0 = -1e30f, mx1 = -1e30f;
        #pragma unroll
        for (int nt = 0; nt < 8; ++nt) {
            #pragma unroll
            for (int j = 0; j < 4; ++j) sc[nt][j] *= 0.125f;
            mx0 = fmaxf(mx0, fmaxf(sc[nt][0], sc[nt][1]));
            mx1 = fmaxf(mx1, fmaxf(sc[nt][2], sc[nt][3]));
        }
        mx0 = fmaxf(mx0, __shfl_xor_sync(0xffffffffu, mx0, 1));
        mx0 = fmaxf(mx0, __shfl_xor_sync(0xffffffffu, mx0, 2));
        mx1 = fmaxf(mx1, __shfl_xor_sync(0xffffffffu, mx1, 1));
        mx1 = fmaxf(mx1, __shfl_xor_sync(0xffffffffu, mx1, 2));
        const float mn0 = fmaxf(mrow[0], mx0), mn1 = fmaxf(mrow[1], mx1);
        const float cor0 = __expf(mrow[0] - mn0), cor1 = __expf(mrow[1] - mn1);

        uint32_t pH[8][2];
        float rs0 = 0.f, rs1 = 0.f;
        #pragma unroll
        for (int nt = 0; nt < 8; ++nt) {
            const float p0 = __expf(sc[nt][0] - mn0);
            const float p1 = __expf(sc[nt][1] - mn0);
            const float p2 = __expf(sc[nt][2] - mn1);
            const float p3 = __expf(sc[nt][3] - mn1);
            rs0 += p0 + p1; rs1 += p2 + p3;
            pH[nt][0] = pack_h2(__float2half(p0), __float2half(p1));
            pH[nt][1] = pack_h2(__float2half(p2), __float2half(p3));
        }
        rs0 += __shfl_xor_sync(0xffffffffu, rs0, 1);
        rs0 += __shfl_xor_sync(0xffffffffu, rs0, 2);
        rs1 += __shfl_xor_sync(0xffffffffu, rs1, 1);
        rs1 += __shfl_xor_sync(0xffffffffu, rs1, 2);
        lrow[0] = lrow[0] * cor0 + rs0;
        lrow[1] = lrow[1] * cor1 + rs1;
        mrow[0] = mn0; mrow[1] = mn1;
        #pragma unroll
        for (int nt = 0; nt < 8; ++nt) {
            oacc[nt][0] *= cor0; oacc[nt][1] *= cor0;
            oacc[nt][2] *= cor1; oacc[nt][3] *= cor1;
        }

        #pragma unroll
        for (int ks = 0; ks < 4; ++ks) {
            uint32_t aPh[4] = {pH[2*ks][0], pH[2*ks][1], pH[2*ks+1][0], pH[2*ks+1][1]};
            uint32_t bVh[8][2];
            #pragma unroll
            for (int p = 0; p < 4; ++p) {
                const int br = p * 16 + l15;
                const uint32_t bc = ((uint32_t)((ks * 2 + lk) ^ (br & 7)) << 4)
                                  + (uint32_t)br * 128;
                uint32_t r0, r1, r2, r3;
                LDSM_X4(r0, r1, r2, r3, bufb + 8192 + bc);
                bVh[2*p][0] = r0; bVh[2*p][1] = r2;
                bVh[2*p+1][0] = r1; bVh[2*p+1][1] = r3;
            }
            #pragma unroll
            for (int nt = 0; nt < 8; ++nt)
                MMA16816(oacc[nt], aPh, bVh[nt]);
        }
        __syncthreads();
    }

    const int g = lane >> 2, t2 = 2 * (lane & 3);
    const float inv0 = 1.f / lrow[0], inv1 = 1.f / lrow[1];
    const long qr0 = (long)(b * SQL + q0 + warp * 16 + g);
    #pragma unroll
    for (int nt = 0; nt < 8; ++nt) {
        const int d = h * DH + nt * 8 + t2;
        float2 o0; o0.x = oacc[nt][0] * inv0; o0.y = oacc[nt][1] * inv0;
        float2 o1; o1.x = oacc[nt][2] * inv1; o1.y = oacc[nt][3] * inv1;
        *(float2*)(out + qr0 * DM + d) = o0;
        *(float2*)(out + (qr0 + 8) * DM + d) = o1;
    }
}

// ---------------- launch -----------------------------------------------------
extern "C" void kernel_launch(void* const* d_in, const int* in_sizes, int n_in,
                              void* d_out, int out_size)
{
    const float* hs   = (const float*)d_in[0];
    const float* ctx  = (const float*)d_in[1];
    const float* Wq   = (const float*)d_in[2];
    const float* bq   = (const float*)d_in[3];
    const float* Wk   = (const float*)d_in[4];
    const float* bk   = (const float*)d_in[5];
    const float* Wv   = (const float*)d_in[6];
    const float* bv   = (const float*)d_in[7];
    const float* Wobs = (const float*)d_in[8];
    const float* bobs = (const float*)d_in[9];
    const float* Wmat = (const float*)d_in[10];
    const float* bmat = (const float*)d_in[11];
    const float* lng  = (const float*)d_in[12];
    const float* lnb  = (const float*)d_in[13];
    float* out = (float*)d_out;

    float *pv, *ps, *pnq, *pnk;
    __half *hsh, *ctxh, *qh, *kh, *vTh, *ph, *gh;
    __half *Wqh, *Wkh, *Wvh, *Woh, *Wmh;
    __half *mqh, *mql, *mkh;
    cudaGetSymbolAddress((void**)&pv,   g_v);
    cudaGetSymbolAddress((void**)&ps,   g_s);
    cudaGetSymbolAddress((void**)&pnq,  g_newq);
    cudaGetSymbolAddress((void**)&pnk,  g_newk);
    cudaGetSymbolAddress((void**)&hsh,  g_hsh);
    cudaGetSymbolAddress((void**)&ctxh, g_ctxh);
    cudaGetSymbolAddress((void**)&qh,   g_qh);
    cudaGetSymbolAddress((void**)&kh,   g_kh);
    cudaGetSymbolAddress((void**)&vTh,  g_vTh);
    cudaGetSymbolAddress((void**)&ph,   g_ph);
    cudaGetSymbolAddress((void**)&gh,   g_gh);
    cudaGetSymbolAddress((void**)&Wqh,  g_Wqh);
    cudaGetSymbolAddress((void**)&Wkh,  g_Wkh);
    cudaGetSymbolAddress((void**)&Wvh,  g_Wvh);
    cudaGetSymbolAddress((void**)&Woh,  g_Woh);
    cudaGetSymbolAddress((void**)&Wmh,  g_Wmh);
    cudaGetSymbolAddress((void**)&mqh,  g_mqh);
    cudaGetSymbolAddress((void**)&mql,  g_mql);
    cudaGetSymbolAddress((void**)&mkh,  g_mkh);

    cudaFuncSetAttribute(mma_gemm<false, true>,
                         cudaFuncAttributeMaxDynamicSharedMemorySize, GEMM_SMEM);
    cudaFuncSetAttribute(mma_gemm<true, true>,
                         cudaFuncAttributeMaxDynamicSharedMemorySize, GEMM_SMEM);
    cudaFuncSetAttribute(mma_gemm<true, false>,
                         cudaFuncAttributeMaxDynamicSharedMemorySize, GEMM_SMEM);
    cudaFuncSetAttribute(mma_gemm<false, false>,
                         cudaFuncAttributeMaxDynamicSharedMemorySize, GEMM_SMEM);
    cudaFuncSetAttribute(mha_mma_kernel,
                         cudaFuncAttributeMaxDynamicSharedMemorySize, MHA_SMEM);

    const dim3 T(256);
    const dim3 gProj(8, 64, 1);      // N=1024, M=8192
    const dim3 gBat(8, 8, 8);        // N=1024, M=1024, batch 8
    const long sQ = 1024L * 1024;    // per-batch stride (dense 1024-wide)

    // input conversions: two big activations + one merged weights kernel
    convert_h<<<1184, T>>>(hs,  hsh,  8192L * 512);
    convert_h<<<1184, T>>>(ctx, ctxh, 8192L * 512);
    CvtW cw;
    cw.s0 = Wq;   cw.d0 = Wqh;
    cw.s1 = Wk;   cw.d1 = Wkh;
    cw.s2 = Wv;   cw.d2 = Wvh;
    cw.s3 = Wobs; cw.d3 = Woh;
    cw.s4 = Wmat; cw.d4 = Wmh;
    convert_w5<<<1480, T>>>(cw);

    // projections
    mma_gemm<false, true><<<gProj, T, GEMM_SMEM>>>(hsh,  Wqh, bq, nullptr, qh,
                                                   1024, 1.f, 0, 0, 0, 0);
    mma_gemm<false, true><<<gProj, T, GEMM_SMEM>>>(ctxh, Wkh, bk, nullptr, kh,
                                                   1024, 1.f, 0, 0, 0, 0);
    mma_gemm<true, true><<<gProj, T, GEMM_SMEM>>>(ctxh, Wvh, bv, pv, nullptr,
                                                  1024, 1.f, 0, 0, 0, 0);
    transconv_v<<<dim3(32, 32, 8), T>>>(pv, vTh);

    // guide block: S = q_hi @ k_hi^T / 32, softmax, P_hi @ V_hi
    mma_gemm<true, false><<<gBat, T, GEMM_SMEM>>>(qh, kh, nullptr, ps, nullptr,
                                                  1024, 0.03125f, sQ, sQ, sQ, 0);
    softmax_h<<<BB * SQL, T>>>(ps, ph);
    mma_gemm<false, false><<<gBat, T, GEMM_SMEM>>>(ph, vTh, nullptr, nullptr, gh,
                                                   1024, 1.f, sQ, sQ, 0, sQ);

    // obs / mat projections + fused ReLU+LN
    mma_gemm<true, true><<<gProj, T, GEMM_SMEM>>>(gh, Woh, bobs, pnq, nullptr,
                                                  1024, 1.f, 0, 0, 0, 0);
    relu_ln_split<<<BB * SQL, T>>>(pnq, lng, lnb, mqh, mql);
    mma_gemm<true, true><<<gProj, T, GEMM_SMEM>>>(kh, Wmh, bmat, pnk, nullptr,
                                                  1024, 1.f, 0, 0, 0, 0);
    relu_ln_split<<<BB * SKL, T>>>(pnk, lng, lnb, mkh, nullptr);

    // tensor-core multi-head attention
    mha_mma_kernel<<<dim3(SQL / 128, BB * NH), T, MHA_SMEM>>>(
        mqh, mql, mkh, vTh, out);
}

// round 15
// speedup vs baseline: 1.5352x; 1.5352x over previous
#include <cuda_runtime.h>
#include <cuda_fp16.h>
#include <math.h>
#include <stdint.h>

#define BB 8
#define SQL 1024
#define SKL 1024
#define DM  1024
#define NH  16
#define DH  64

// ---------------- scratch (static device arrays; no cudaMalloc) -------------
__device__ float g_v   [BB*SKL*DM];
__device__ float g_s   [(long)BB*SQL*SKL];
__device__ float g_newq[BB*SQL*DM];
__device__ float g_newk[BB*SKL*DM];

__device__ __half g_hsh [8192L*1024];
__device__ __half g_ctxh[8192L*1024];
__device__ __half g_qh  [8192L*1024];
__device__ __half g_kh  [8192L*1024];
__device__ __half g_vTh [8192L*1024];
__device__ __half g_ph  [8192L*1024];
__device__ __half g_gh  [8192L*1024];
__device__ __half g_Wqh [1024L*1024];
__device__ __half g_Wkh [1024L*1024];
__device__ __half g_Wvh [1024L*1024];
__device__ __half g_Woh [1024L*1024];
__device__ __half g_Wmh [1024L*1024];
// LayerNorm outputs for MHA
__device__ __half g_mqh[8192L*1024];
__device__ __half g_mql[8192L*1024];
__device__ __half g_mkh[8192L*1024];

// ---------------- helpers ----------------------------------------------------
__device__ __forceinline__ uint32_t smem_u32(const void* p) {
    uint32_t a;
    asm("{ .reg .u64 t; cvta.to.shared.u64 t, %1; cvt.u32.u64 %0, t; }"
        : "=r"(a) : "l"(p));
    return a;
}
#define CP_ASYNC16(sa, ga) \
    asm volatile("cp.async.cg.shared.global [%0], [%1], 16;" :: "r"(sa), "l"(ga))
#define CP_COMMIT() asm volatile("cp.async.commit_group;" ::: "memory")
#define CP_WAIT1()  asm volatile("cp.async.wait_group 1;" ::: "memory")
#define CP_WAIT2()  asm volatile("cp.async.wait_group 2;" ::: "memory")

#define LDSM_X4(r0, r1, r2, r3, a) \
    asm volatile("ldmatrix.sync.aligned.m8n8.x4.shared.b16 {%0,%1,%2,%3}, [%4];" \
        : "=r"(r0), "=r"(r1), "=r"(r2), "=r"(r3) : "r"(a))

#define MMA16816(c, a, b) \
    asm volatile("mma.sync.aligned.m16n8k16.row.col.f32.f16.f16.f32 " \
        "{%0,%1,%2,%3}, {%4,%5,%6,%7}, {%8,%9}, {%0,%1,%2,%3};" \
        : "+f"((c)[0]), "+f"((c)[1]), "+f"((c)[2]), "+f"((c)[3]) \
        : "r"((a)[0]), "r"((a)[1]), "r"((a)[2]), "r"((a)[3]), \
          "r"((b)[0]), "r"((b)[1]))

__device__ __forceinline__ uint32_t pack_h2(__half a, __half b) {
    __half2 t = __halves2half2(a, b);
    return *(uint32_t*)&t;
}

// ---------------- HMMA GEMM: 128x128 tile, K=1024, 4-stage, 2 CTA/SM ---------
// (R13 winner, verbatim: full unroll allowed, runtime-null output selection.)
// A [M, 1024] fp16 K-major, B [N_, 1024] fp16 K-major.
// Outputs (any subset):  Cf : f32 [M, N];  Ch : fp16 [M, N]
#define STAGES 4
#define STAGE_BYTES 16384
#define GEMM_SMEM (STAGES * STAGE_BYTES)   // 65536
#define KK 1024

__global__ void __launch_bounds__(256, 2) mma_gemm(
    const __half* __restrict__ A, const __half* __restrict__ B,
    const float* __restrict__ bias,
    float* __restrict__ Cf, __half* __restrict__ Ch,
    int N, float alpha, long sA, long sB, long sCf, long sCh)
{
    extern __shared__ char smem[];
    const uint32_t sbase = smem_u32(smem);
    const int tid = threadIdx.x, warp = tid >> 5, lane = tid & 31;
    const int wM = warp >> 1, wN = warp & 1;
    const long bm = (long)blockIdx.y * 128, bn = (long)blockIdx.x * 128;
    const int z = blockIdx.z;

    const int lrow = tid >> 1;
    const int lc0 = (tid & 1) * 2;
    const __half* Ag = A + z * sA + (bm + lrow) * (long)KK + lc0 * 8;
    const __half* Bg = B + z * sB + (bn + lrow) * (long)KK + lc0 * 8;
    const uint32_t sw = (uint32_t)((lrow >> 1) & 3);
    const uint32_t soff0 = (uint32_t)lrow * 64 + (((uint32_t)lc0     ^ sw) << 4);
    const uint32_t soff1 = (uint32_t)lrow * 64 + (((uint32_t)(lc0+1) ^ sw) << 4);

    float acc[2][8][4];
    #pragma unroll
    for (int i = 0; i < 2; ++i)
        #pragma unroll
        for (int j = 0; j < 8; ++j)
            #pragma unroll
            for (int k = 0; k < 4; ++k) acc[i][j][k] = 0.f;

    const int NCH = KK / 32;   // 32

    #pragma unroll
    for (int s = 0; s < STAGES - 1; ++s) {
        const uint32_t st = sbase + s * STAGE_BYTES;
        CP_ASYNC16(st + soff0,        Ag + (long)s * 32);
        CP_ASYNC16(st + soff1,        Ag + (long)s * 32 + 8);
        CP_ASYNC16(st + 8192 + soff0, Bg + (long)s * 32);
        CP_ASYNC16(st + 8192 + soff1, Bg + (long)s * 32 + 8);
        CP_COMMIT();
    }

    const int l15 = lane & 15;
    const int lk  = lane >> 4;

    for (int c = 0; c < NCH; ++c) {
        CP_WAIT2();
        __syncthreads();

        const int nc = c + STAGES - 1;
        if (nc < NCH) {
            const uint32_t st = sbase + (nc % STAGES) * STAGE_BYTES;
            CP_ASYNC16(st + soff0,        Ag + (long)nc * 32);
            CP_ASYNC16(st + soff1,        Ag + (long)nc * 32 + 8);
            CP_ASYNC16(st + 8192 + soff0, Bg + (long)nc * 32);
            CP_ASYNC16(st + 8192 + soff1, Bg + (long)nc * 32 + 8);
        }
        CP_COMMIT();

        const uint32_t aB = sbase + (c % STAGES) * STAGE_BYTES;
        const uint32_t bB = aB + 8192;
        #pragma unroll
        for (int ks = 0; ks < 2; ++ks) {
            uint32_t a[2][4], b[8][2];
            #pragma unroll
            for (int mt = 0; mt < 2; ++mt) {
                const int row = wM * 32 + mt * 16 + l15;
                const uint32_t kc = (uint32_t)(ks * 2 + lk);
                const uint32_t ad = aB + row * 64 + ((kc ^ ((row >> 1) & 3)) << 4);
                LDSM_X4(a[mt][0], a[mt][1], a[mt][2], a[mt][3], ad);
            }
            #pragma unroll
            for (int p = 0; p < 4; ++p) {
                const int row = wN * 64 + p * 16 + l15;
                const uint32_t kc = (uint32_t)(ks * 2 + lk);
                const uint32_t bd = bB + row * 64 + ((kc ^ ((row >> 1) & 3)) << 4);
                uint32_t r0, r1, r2, r3;
                LDSM_X4(r0, r1, r2, r3, bd);
                b[2 * p][0] = r0; b[2 * p][1] = r2;
                b[2 * p + 1][0] = r1; b[2 * p + 1][1] = r3;
            }
            #pragma unroll
            for (int mt = 0; mt < 2; ++mt)
                #pragma unroll
                for (int nt = 0; nt < 8; ++nt)
                    MMA16816(acc[mt][nt], a[mt], b[nt]);
        }
    }

    const int g = lane >> 2, t2 = 2 * (lane & 3);
    #pragma unroll
    for (int mt = 0; mt < 2; ++mt) {
        const long r0 = bm + wM * 32 + mt * 16 + g;
        const long r1 = r0 + 8;
        #pragma unroll
        for (int nt = 0; nt < 8; ++nt) {
            const int gcol = (int)bn + wN * 64 + nt * 8 + t2;
            float v00 = acc[mt][nt][0] * alpha, v01 = acc[mt][nt][1] * alpha;
            float v10 = acc[mt][nt][2] * alpha, v11 = acc[mt][nt][3] * alpha;
            if (bias) {
                const float2 bb = *(const float2*)(bias + gcol);
                v00 += bb.x; v01 += bb.y; v10 += bb.x; v11 += bb.y;
            }
            if (Cf) {
                float2 o0; o0.x = v00; o0.y = v01;
                float2 o1; o1.x = v10; o1.y = v11;
                *(float2*)(Cf + z * sCf + r0 * (long)N + gcol) = o0;
                *(float2*)(Cf + z * sCf + r1 * (long)N + gcol) = o1;
            }
            if (Ch) {
                *(__half2*)(Ch + z * sCh + r0 * (long)N + gcol) =
                    __halves2half2(__float2half(v00), __float2half(v01));
                *(__half2*)(Ch + z * sCh + r1 * (long)N + gcol) =
                    __halves2half2(__float2half(v10), __float2half(v11));
            }
        }
    }
}

// ---------------- merged f32 -> fp16 conversion: 2 activations ---------------
// Both segments exactly 2^22 float2 pairs: segment = p >> 22, offset masked.
#define ASEG 4194304L
__global__ void __launch_bounds__(256) convert_a2(
    const float* __restrict__ s0, const float* __restrict__ s1,
    __half* __restrict__ d0, __half* __restrict__ d1)
{
    const long total = 2 * ASEG;
    for (long p = blockIdx.x * (long)blockDim.x + threadIdx.x; p < total;
         p += (long)gridDim.x * blockDim.x) {
        const int w = (int)(p >> 22);
        const long off = p & (ASEG - 1);
        const float* src = w ? s1 : s0;
        __half* dst = w ? d1 : d0;
        float2 x = ((const float2*)src)[off];
        ((__half2*)dst)[off] = __halves2half2(__float2half(x.x), __float2half(x.y));
    }
}

// ---------------- merged f32 -> fp16 conversion for the 5 weights ------------
#define WSEG 524288L
struct CvtW {
    const float *s0, *s1, *s2, *s3, *s4;
    __half *d0, *d1, *d2, *d3, *d4;
};
__global__ void __launch_bounds__(256) convert_w5(CvtW a)
{
    const long total = 5 * WSEG;
    for (long p = blockIdx.x * (long)blockDim.x + threadIdx.x; p < total;
         p += (long)gridDim.x * blockDim.x) {
        const int w = (int)(p >> 19);
        const long off = p & (WSEG - 1);
        const float* src = (w == 0) ? a.s0 : (w == 1) ? a.s1 : (w == 2) ? a.s2
                         : (w == 3) ? a.s3 : a.s4;
        __half* dst = (w == 0) ? a.d0 : (w == 1) ? a.d1 : (w == 2) ? a.d2
                    : (w == 3) ? a.d3 : a.d4;
        float2 x = ((const float2*)src)[off];
        ((__half2*)dst)[off] = __halves2half2(__float2half(x.x), __float2half(x.y));
    }
}

// ---------------- v [B,SK,D] f32 -> vT fp16 [B, D, SK] -----------------------
__global__ void __launch_bounds__(256) transconv_v(
    const float* __restrict__ v, __half* __restrict__ out)
{
    __shared__ float t[32][33];
    const int d0 = blockIdx.x * 32, s0 = blockIdx.y * 32, b = blockIdx.z;
    const int tx = threadIdx.x & 31, ty = threadIdx.x >> 5;
    #pragma unroll
    for (int i = 0; i < 32; i += 8)
        t[ty + i][tx] = v[((long)b * SKL + s0 + ty + i) * DM + d0 + tx];
    __syncthreads();
    #pragma unroll
    for (int i = 0; i < 32; i += 8) {
        const int d = d0 + ty + i, s = s0 + tx;
        out[((long)b * DM + d) * (long)SKL + s] = __float2half(t[tx][ty + i]);
    }
}

// ---------------- block reductions -------------------------------------------
__device__ __forceinline__ float block_reduce_max(float v) {
    __shared__ float sh[8];
    int lane = threadIdx.x & 31, wid = threadIdx.x >> 5;
    #pragma unroll
    for (int o = 16; o; o >>= 1) v = fmaxf(v, __shfl_xor_sync(0xffffffffu, v, o));
    if (lane == 0) sh[wid] = v;
    __syncthreads();
    if (threadIdx.x == 0) {
        float r = sh[0];
        #pragma unroll
        for (int i = 1; i < 8; ++i) r = fmaxf(r, sh[i]);
        sh[0] = r;
    }
    __syncthreads();
    float r = sh[0];
    __syncthreads();
    return r;
}
__device__ __forceinline__ float block_reduce_sum(float v) {
    __shared__ float sh[8];
    int lane = threadIdx.x & 31, wid = threadIdx.x >> 5;
    #pragma unroll
    for (int o = 16; o; o >>= 1) v += __shfl_xor_sync(0xffffffffu, v, o);
    if (lane == 0) sh[wid] = v;
    __syncthreads();
    if (threadIdx.x == 0) {
        float r = sh[0];
        #pragma unroll
        for (int i = 1; i < 8; ++i) r += sh[i];
        sh[0] = r;
    }
    __syncthreads();
    float r = sh[0];
    __syncthreads();
    return r;
}

// ---------------- guide softmax -> fp16 dense (1-pass) -----------------------
__global__ void __launch_bounds__(256) softmax_h(
    const float* __restrict__ x, __half* __restrict__ outh)
{
    x += (long)blockIdx.x * SKL;
    __half2* row = (__half2*)(outh + (long)blockIdx.x * SKL);
    const int tid = threadIdx.x;
    const float4 xv = *(const float4*)(x + tid * 4);
    float lm = fmaxf(fmaxf(xv.x, xv.y), fmaxf(xv.z, xv.w));
    const float m = block_reduce_max(lm);
    float e0 = __expf(xv.x - m), e1 = __expf(xv.y - m);
    float e2 = __expf(xv.z - m), e3 = __expf(xv.w - m);
    const float s = block_reduce_sum(e0 + e1 + e2 + e3);
    const float inv = 1.f / s;
    row[tid * 2]     = __halves2half2(__float2half(e0 * inv), __float2half(e1 * inv));
    row[tid * 2 + 1] = __halves2half2(__float2half(e2 * inv), __float2half(e3 * inv));
}

// ---------------- fused ReLU + LayerNorm -> fp16 hi (+ optional lo) ----------
__global__ void __launch_bounds__(256) relu_ln_split(
    const float* __restrict__ x, const float* __restrict__ g,
    const float* __restrict__ bparm,
    __half* __restrict__ oh, __half* __restrict__ ol)
{
    x  += (long)blockIdx.x * DM;
    oh += (long)blockIdx.x * DM;
    const int tid = threadIdx.x;
    float4 xv = *(const float4*)(x + tid * 4);
    xv.x = fmaxf(xv.x, 0.f); xv.y = fmaxf(xv.y, 0.f);
    xv.z = fmaxf(xv.z, 0.f); xv.w = fmaxf(xv.w, 0.f);
    const float s1 = block_reduce_sum(xv.x + xv.y + xv.z + xv.w);
    const float s2 = block_reduce_sum(xv.x * xv.x + xv.y * xv.y +
                                      xv.z * xv.z + xv.w * xv.w);
    const float mean = s1 / DM;
    const float var  = s2 / DM - mean * mean;
    const float inv  = rsqrtf(var + 1e-5f);
    const float4 gv = *(const float4*)(g + tid * 4);
    const float4 bv = *(const float4*)(bparm + tid * 4);
    float y0 = (xv.x - mean) * inv * gv.x + bv.x;
    float y1 = (xv.y - mean) * inv * gv.y + bv.y;
    float y2 = (xv.z - mean) * inv * gv.z + bv.z;
    float y3 = (xv.w - mean) * inv * gv.w + bv.w;
    __half h0 = __float2half(y0), h1 = __float2half(y1);
    __half h2 = __float2half(y2), h3 = __float2half(y3);
    *(__half2*)(oh + tid * 4)     = __halves2half2(h0, h1);
    *(__half2*)(oh + tid * 4 + 2) = __halves2half2(h2, h3);
    if (ol) {
        ol += (long)blockIdx.x * DM;
        *(__half2*)(ol + tid * 4)     = __halves2half2(
            __float2half(y0 - __half2float(h0)),
            __float2half(y1 - __half2float(h1)));
        *(__half2*)(ol + tid * 4 + 2) = __halves2half2(
            __float2half(y2 - __half2float(h2)),
            __float2half(y3 - __half2float(h3)));
    }
}

// ---------------- tensor-core flash MHA --------------------------------------
// S = QK^T 2-term (Qh,Ql x Kh); PV 1-term (Ph x Vh).
#define MHA_STAGE 16384
#define MHA_SMEM (32768 + 2 * MHA_STAGE)   // 65536
__global__ void __launch_bounds__(256, 1) mha_mma_kernel(
    const __half* __restrict__ qh, const __half* __restrict__ ql,
    const __half* __restrict__ kh,
    const __half* __restrict__ vTh, float* __restrict__ out)
{
    extern __shared__ char smem[];
    const uint32_t sb = smem_u32(smem);
    const uint32_t sQh = sb, sQl = sb + 16384;
    const int tid = threadIdx.x, warp = tid >> 5, lane = tid & 31;
    const int bh = blockIdx.y, b = bh >> 4, h = bh & 15;
    const int q0 = blockIdx.x * 128;

    #pragma unroll
    for (int j = 0; j < 4; ++j) {
        const int idx = tid + j * 256;
        const int r = idx >> 3, c = idx & 7;
        const uint32_t soff = (uint32_t)r * 128 + ((uint32_t)(c ^ (r & 7)) << 4);
        const long gg = ((long)(b * SQL + q0 + r)) * DM + h * DH + c * 8;
        CP_ASYNC16(sQh + soff, qh + gg);
        CP_ASYNC16(sQl + soff, ql + gg);
    }
    auto issue_tile = [&](int t) {
        const uint32_t bufb = sb + 32768 + (uint32_t)(t & 1) * MHA_STAGE;
        #pragma unroll
        for (int j = 0; j < 2; ++j) {
            const int idx = tid + j * 256;
            const int r = idx >> 3, c = idx & 7;
            const uint32_t soff = (uint32_t)r * 128 + ((uint32_t)(c ^ (r & 7)) << 4);
            const long gk = ((long)(b * SKL + t * 64 + r)) * DM + h * DH + c * 8;
            CP_ASYNC16(bufb + soff, kh + gk);
            const long gv = ((long)(b * DM + h * DH + r)) * (long)SKL + t * 64 + c * 8;
            CP_ASYNC16(bufb + 8192 + soff, vTh + gv);
        }
    };
    issue_tile(0);
    CP_COMMIT();

    float oacc[8][4];
    #pragma unroll
    for (int i = 0; i < 8; ++i)
        #pragma unroll
        for (int j = 0; j < 4; ++j) oacc[i][j] = 0.f;
    float mrow[2] = {-1e30f, -1e30f}, lrow[2] = {0.f, 0.f};

    const int l15 = lane & 15, lk = lane >> 4;

    for (int t = 0; t < 16; ++t) {
        if (t + 1 < 16) issue_tile(t + 1);
        CP_COMMIT();
        CP_WAIT1();
        __syncthreads();
        const uint32_t bufb = sb + 32768 + (uint32_t)(t & 1) * MHA_STAGE;

        float sc[8][4];
        #pragma unroll
        for (int i = 0; i < 8; ++i)
            #pragma unroll
            for (int j = 0; j < 4; ++j) sc[i][j] = 0.f;

        #pragma unroll
        for (int ks = 0; ks < 4; ++ks) {
            const int arow = warp * 16 + l15;
            const uint32_t ac = ((uint32_t)((ks * 2 + lk) ^ (arow & 7)) << 4)
                              + (uint32_t)arow * 128;
            uint32_t aH[4], aL[4];
            LDSM_X4(aH[0], aH[1], aH[2], aH[3], sQh + ac);
            LDSM_X4(aL[0], aL[1], aL[2], aL[3], sQl + ac);
            uint32_t bH[8][2];
            #pragma unroll
            for (int p = 0; p < 4; ++p) {
                const int br = p * 16 + l15;
                const uint32_t bc = ((uint32_t)((ks * 2 + lk) ^ (br & 7)) << 4)
                                  + (uint32_t)br * 128;
                uint32_t r0, r1, r2, r3;
                LDSM_X4(r0, r1, r2, r3, bufb + bc);
                bH[2*p][0] = r0; bH[2*p][1] = r2;
                bH[2*p+1][0] = r1; bH[2*p+1][1] = r3;
            }
            #pragma unroll
            for (int nt = 0; nt < 8; ++nt) {
                MMA16816(sc[nt], aH, bH[nt]);
                MMA16816(sc[nt], aL, bH[nt]);
            }
        }

        float mx0 = -1e30f, mx1 = -1e30f;
        #pragma unroll
        for (int nt = 0; nt < 8; ++nt) {
            #pragma unroll
            for (int j = 0; j < 4; ++j) sc[nt][j] *= 0.125f;
            mx0 = fmaxf(mx0, fmaxf(sc[nt][0], sc[nt][1]));
            mx1 = fmaxf(mx1, fmaxf(sc[nt][2], sc[nt][3]));
        }
        mx0 = fmaxf(mx0, __shfl_xor_sync(0xffffffffu, mx0, 1));
        mx0 = fmaxf(mx0, __shfl_xor_sync(0xffffffffu, mx0, 2));
        mx1 = fmaxf(mx1, __shfl_xor_sync(0xffffffffu, mx1, 1));
        mx1 = fmaxf(mx1, __shfl_xor_sync(0xffffffffu, mx1, 2));
        const float mn0 = fmaxf(mrow[0], mx0), mn1 = fmaxf(mrow[1], mx1);
        const float cor0 = __expf(mrow[0] - mn0), cor1 = __expf(mrow[1] - mn1);

        uint32_t pH[8][2];
        float rs0 = 0.f, rs1 = 0.f;
        #pragma unroll
        for (int nt = 0; nt < 8; ++nt) {
            const float p0 = __expf(sc[nt][0] - mn0);
            const float p1 = __expf(sc[nt][1] - mn0);
            const float p2 = __expf(sc[nt][2] - mn1);
            const float p3 = __expf(sc[nt][3] - mn1);
            rs0 += p0 + p1; rs1 += p2 + p3;
            pH[nt][0] = pack_h2(__float2half(p0), __float2half(p1));
            pH[nt][1] = pack_h2(__float2half(p2), __float2half(p3));
        }
        rs0 += __shfl_xor_sync(0xffffffffu, rs0, 1);
        rs0 += __shfl_xor_sync(0xffffffffu, rs0, 2);
        rs1 += __shfl_xor_sync(0xffffffffu, rs1, 1);
        rs1 += __shfl_xor_sync(0xffffffffu, rs1, 2);
        lrow[0] = lrow[0] * cor0 + rs0;
        lrow[1] = lrow[1] * cor1 + rs1;
        mrow[0] = mn0; mrow[1] = mn1;
        #pragma unroll
        for (int nt = 0; nt < 8; ++nt) {
            oacc[nt][0] *= cor0; oacc[nt][1] *= cor0;
            oacc[nt][2] *= cor1; oacc[nt][3] *= cor1;
        }

        #pragma unroll
        for (int ks = 0; ks < 4; ++ks) {
            uint32_t aPh[4] = {pH[2*ks][0], pH[2*ks][1], pH[2*ks+1][0], pH[2*ks+1][1]};
            uint32_t bVh[8][2];
            #pragma unroll
            for (int p = 0; p < 4; ++p) {
                const int br = p * 16 + l15;
                const uint32_t bc = ((uint32_t)((ks * 2 + lk) ^ (br & 7)) << 4)
                                  + (uint32_t)br * 128;
                uint32_t r0, r1, r2, r3;
                LDSM_X4(r0, r1, r2, r3, bufb + 8192 + bc);
                bVh[2*p][0] = r0; bVh[2*p][1] = r2;
                bVh[2*p+1][0] = r1; bVh[2*p+1][1] = r3;
            }
            #pragma unroll
            for (int nt = 0; nt < 8; ++nt)
                MMA16816(oacc[nt], aPh, bVh[nt]);
        }
        __syncthreads();
    }

    const int g = lane >> 2, t2 = 2 * (lane & 3);
    const float inv0 = 1.f / lrow[0], inv1 = 1.f / lrow[1];
    const long qr0 = (long)(b * SQL + q0 + warp * 16 + g);
    #pragma unroll
    for (int nt = 0; nt < 8; ++nt) {
        const int d = h * DH + nt * 8 + t2;
        float2 o0; o0.x = oacc[nt][0] * inv0; o0.y = oacc[nt][1] * inv0;
        float2 o1; o1.x = oacc[nt][2] * inv1; o1.y = oacc[nt][3] * inv1;
        *(float2*)(out + qr0 * DM + d) = o0;
        *(float2*)(out + (qr0 + 8) * DM + d) = o1;
    }
}

// ---------------- launch -----------------------------------------------------
extern "C" void kernel_launch(void* const* d_in, const int* in_sizes, int n_in,
                              void* d_out, int out_size)
{
    const float* hs   = (const float*)d_in[0];
    const float* ctx  = (const float*)d_in[1];
    const float* Wq   = (const float*)d_in[2];
    const float* bq   = (const float*)d_in[3];
    const float* Wk   = (const float*)d_in[4];
    const float* bk   = (const float*)d_in[5];
    const float* Wv   = (const float*)d_in[6];
    const float* bv   = (const float*)d_in[7];
    const float* Wobs = (const float*)d_in[8];
    const float* bobs = (const float*)d_in[9];
    const float* Wmat = (const float*)d_in[10];
    const float* bmat = (const float*)d_in[11];
    const float* lng  = (const float*)d_in[12];
    const float* lnb  = (const float*)d_in[13];
    float* out = (float*)d_out;

    float *pv, *ps, *pnq, *pnk;
    __half *hsh, *ctxh, *qh, *kh, *vTh, *ph, *gh;
    __half *Wqh, *Wkh, *Wvh, *Woh, *Wmh;
    __half *mqh, *mql, *mkh;
    cudaGetSymbolAddress((void**)&pv,   g_v);
    cudaGetSymbolAddress((void**)&ps,   g_s);
    cudaGetSymbolAddress((void**)&pnq,  g_newq);
    cudaGetSymbolAddress((void**)&pnk,  g_newk);
    cudaGetSymbolAddress((void**)&hsh,  g_hsh);
    cudaGetSymbolAddress((void**)&ctxh, g_ctxh);
    cudaGetSymbolAddress((void**)&qh,   g_qh);
    cudaGetSymbolAddress((void**)&kh,   g_kh);
    cudaGetSymbolAddress((void**)&vTh,  g_vTh);
    cudaGetSymbolAddress((void**)&ph,   g_ph);
    cudaGetSymbolAddress((void**)&gh,   g_gh);
    cudaGetSymbolAddress((void**)&Wqh,  g_Wqh);
    cudaGetSymbolAddress((void**)&Wkh,  g_Wkh);
    cudaGetSymbolAddress((void**)&Wvh,  g_Wvh);
    cudaGetSymbolAddress((void**)&Woh,  g_Woh);
    cudaGetSymbolAddress((void**)&Wmh,  g_Wmh);
    cudaGetSymbolAddress((void**)&mqh,  g_mqh);
    cudaGetSymbolAddress((void**)&mql,  g_mql);
    cudaGetSymbolAddress((void**)&mkh,  g_mkh);

    cudaFuncSetAttribute(mma_gemm, cudaFuncAttributeMaxDynamicSharedMemorySize,
                         GEMM_SMEM);
    cudaFuncSetAttribute(mha_mma_kernel, cudaFuncAttributeMaxDynamicSharedMemorySize,
                         MHA_SMEM);

    const dim3 T(256);
    const dim3 gProj(8, 64, 1);      // N=1024, M=8192
    const dim3 gBat(8, 8, 8);        // N=1024, M=1024, batch 8
    const long sQ = 1024L * 1024;    // per-batch stride (dense 1024-wide)

    // input conversions: one merged activation kernel + one merged weights kernel
    convert_a2<<<2368, T>>>(hs, ctx, hsh, ctxh);
    CvtW cw;
    cw.s0 = Wq;   cw.d0 = Wqh;
    cw.s1 = Wk;   cw.d1 = Wkh;
    cw.s2 = Wv;   cw.d2 = Wvh;
    cw.s3 = Wobs; cw.d3 = Woh;
    cw.s4 = Wmat; cw.d4 = Wmh;
    convert_w5<<<1480, T>>>(cw);

    // projections
    mma_gemm<<<gProj, T, GEMM_SMEM>>>(hsh,  Wqh, bq, nullptr, qh,
                                      1024, 1.f, 0, 0, 0, 0);
    mma_gemm<<<gProj, T, GEMM_SMEM>>>(ctxh, Wkh, bk, nullptr, kh,
                                      1024, 1.f, 0, 0, 0, 0);
    mma_gemm<<<gProj, T, GEMM_SMEM>>>(ctxh, Wvh, bv, pv, nullptr,
                                      1024, 1.f, 0, 0, 0, 0);
    transconv_v<<<dim3(32, 32, 8), T>>>(pv, vTh);

    // guide block: S = q_hi @ k_hi^T / 32, softmax, P_hi @ V_hi
    mma_gemm<<<gBat, T, GEMM_SMEM>>>(qh, kh, nullptr, ps, nullptr,
                                     1024, 0.03125f, sQ, sQ, sQ, 0);
    softmax_h<<<BB * SQL, T>>>(ps, ph);
    mma_gemm<<<gBat, T, GEMM_SMEM>>>(ph, vTh, nullptr, nullptr, gh,
                                     1024, 1.f, sQ, sQ, 0, sQ);

    // obs / mat projections + fused ReLU+LN
    mma_gemm<<<gProj, T, GEMM_SMEM>>>(gh, Woh, bobs, pnq, nullptr,
                                      1024, 1.f, 0, 0, 0, 0);
    relu_ln_split<<<BB * SQL, T>>>(pnq, lng, lnb, mqh, mql);
    mma_gemm<<<gProj, T, GEMM_SMEM>>>(kh, Wmh, bmat, pnk, nullptr,
                                      1024, 1.f, 0, 0, 0, 0);
    relu_ln_split<<<BB * SKL, T>>>(pnk, lng, lnb, mkh, nullptr);

    // tensor-core multi-head attention
    mha_mma_kernel<<<dim3(SQL / 128, BB * NH), T, MHA_SMEM>>>(
        mqh, mql, mkh, vTh, out);
}

// round 16
// speedup vs baseline: 1.6106x; 1.0491x over previous
#include <cuda_runtime.h>
#include <cuda_fp16.h>
#include <math.h>
#include <stdint.h>

#define BB 8
#define SQL 1024
#define SKL 1024
#define DM  1024
#define NH  16
#define DH  64

// ---------------- scratch (static device arrays; no cudaMalloc) -------------
__device__ float g_v   [BB*SKL*DM];
__device__ float g_s   [(long)BB*SQL*SKL];
__device__ float g_newq[BB*SQL*DM];
__device__ float g_newk[BB*SKL*DM];

__device__ __half g_hsh [8192L*1024];
__device__ __half g_ctxh[8192L*1024];
__device__ __half g_qh  [8192L*1024];
__device__ __half g_kh  [8192L*1024];
__device__ __half g_vTh [8192L*1024];
__device__ __half g_ph  [8192L*1024];
__device__ __half g_gh  [8192L*1024];
__device__ __half g_Wqh [1024L*1024];
__device__ __half g_Wkh [1024L*1024];
__device__ __half g_Wvh [1024L*1024];
__device__ __half g_Woh [1024L*1024];
__device__ __half g_Wmh [1024L*1024];
// LayerNorm outputs for MHA
__device__ __half g_mqh[8192L*1024];
__device__ __half g_mql[8192L*1024];
__device__ __half g_mkh[8192L*1024];

// ---------------- helpers ----------------------------------------------------
__device__ __forceinline__ uint32_t smem_u32(const void* p) {
    uint32_t a;
    asm("{ .reg .u64 t; cvta.to.shared.u64 t, %1; cvt.u32.u64 %0, t; }"
        : "=r"(a) : "l"(p));
    return a;
}
#define CP_ASYNC16(sa, ga) \
    asm volatile("cp.async.cg.shared.global [%0], [%1], 16;" :: "r"(sa), "l"(ga))
#define CP_COMMIT() asm volatile("cp.async.commit_group;" ::: "memory")
#define CP_WAIT1()  asm volatile("cp.async.wait_group 1;" ::: "memory")
#define CP_WAIT2()  asm volatile("cp.async.wait_group 2;" ::: "memory")

#define LDSM_X4(r0, r1, r2, r3, a) \
    asm volatile("ldmatrix.sync.aligned.m8n8.x4.shared.b16 {%0,%1,%2,%3}, [%4];" \
        : "=r"(r0), "=r"(r1), "=r"(r2), "=r"(r3) : "r"(a))

#define MMA16816(c, a, b) \
    asm volatile("mma.sync.aligned.m16n8k16.row.col.f32.f16.f16.f32 " \
        "{%0,%1,%2,%3}, {%4,%5,%6,%7}, {%8,%9}, {%0,%1,%2,%3};" \
        : "+f"((c)[0]), "+f"((c)[1]), "+f"((c)[2]), "+f"((c)[3]) \
        : "r"((a)[0]), "r"((a)[1]), "r"((a)[2]), "r"((a)[3]), \
          "r"((b)[0]), "r"((b)[1]))

__device__ __forceinline__ uint32_t pack_h2(__half a, __half b) {
    __half2 t = __halves2half2(a, b);
    return *(uint32_t*)&t;
}

#define STAGES 4
#define STAGE_BYTES 16384
#define GEMM_SMEM (STAGES * STAGE_BYTES)   // 65536
#define KK 1024

// ---------------- shared GEMM body (128x128 tile, K=1024, 4-stage) -----------
// Identical instruction stream to the R13/R15 winner; pointer bases only.
__device__ __forceinline__ void gemm_body(
    const __half* __restrict__ A, const __half* __restrict__ B,
    const float* __restrict__ bias,
    float* __restrict__ Cf, __half* __restrict__ Ch,
    long bm, long bn, char* smem)
{
    const uint32_t sbase = smem_u32(smem);
    const int tid = threadIdx.x, warp = tid >> 5, lane = tid & 31;
    const int wM = warp >> 1, wN = warp & 1;

    const int lrow = tid >> 1;
    const int lc0 = (tid & 1) * 2;
    const __half* Ag = A + (bm + lrow) * (long)KK + lc0 * 8;
    const __half* Bg = B + (bn + lrow) * (long)KK + lc0 * 8;
    const uint32_t sw = (uint32_t)((lrow >> 1) & 3);
    const uint32_t soff0 = (uint32_t)lrow * 64 + (((uint32_t)lc0     ^ sw) << 4);
    const uint32_t soff1 = (uint32_t)lrow * 64 + (((uint32_t)(lc0+1) ^ sw) << 4);

    float acc[2][8][4];
    #pragma unroll
    for (int i = 0; i < 2; ++i)
        #pragma unroll
        for (int j = 0; j < 8; ++j)
            #pragma unroll
            for (int k = 0; k < 4; ++k) acc[i][j][k] = 0.f;

    const int NCH = KK / 32;   // 32

    #pragma unroll
    for (int s = 0; s < STAGES - 1; ++s) {
        const uint32_t st = sbase + s * STAGE_BYTES;
        CP_ASYNC16(st + soff0,        Ag + (long)s * 32);
        CP_ASYNC16(st + soff1,        Ag + (long)s * 32 + 8);
        CP_ASYNC16(st + 8192 + soff0, Bg + (long)s * 32);
        CP_ASYNC16(st + 8192 + soff1, Bg + (long)s * 32 + 8);
        CP_COMMIT();
    }

    const int l15 = lane & 15;
    const int lk  = lane >> 4;

    for (int c = 0; c < NCH; ++c) {
        CP_WAIT2();
        __syncthreads();

        const int nc = c + STAGES - 1;
        if (nc < NCH) {
            const uint32_t st = sbase + (nc % STAGES) * STAGE_BYTES;
            CP_ASYNC16(st + soff0,        Ag + (long)nc * 32);
            CP_ASYNC16(st + soff1,        Ag + (long)nc * 32 + 8);
            CP_ASYNC16(st + 8192 + soff0, Bg + (long)nc * 32);
            CP_ASYNC16(st + 8192 + soff1, Bg + (long)nc * 32 + 8);
        }
        CP_COMMIT();

        const uint32_t aB = sbase + (c % STAGES) * STAGE_BYTES;
        const uint32_t bB = aB + 8192;
        #pragma unroll
        for (int ks = 0; ks < 2; ++ks) {
            uint32_t a[2][4], b[8][2];
            #pragma unroll
            for (int mt = 0; mt < 2; ++mt) {
                const int row = wM * 32 + mt * 16 + l15;
                const uint32_t kc = (uint32_t)(ks * 2 + lk);
                const uint32_t ad = aB + row * 64 + ((kc ^ ((row >> 1) & 3)) << 4);
                LDSM_X4(a[mt][0], a[mt][1], a[mt][2], a[mt][3], ad);
            }
            #pragma unroll
            for (int p = 0; p < 4; ++p) {
                const int row = wN * 64 + p * 16 + l15;
                const uint32_t kc = (uint32_t)(ks * 2 + lk);
                const uint32_t bd = bB + row * 64 + ((kc ^ ((row >> 1) & 3)) << 4);
                uint32_t r0, r1, r2, r3;
                LDSM_X4(r0, r1, r2, r3, bd);
                b[2 * p][0] = r0; b[2 * p][1] = r2;
                b[2 * p + 1][0] = r1; b[2 * p + 1][1] = r3;
            }
            #pragma unroll
            for (int mt = 0; mt < 2; ++mt)
                #pragma unroll
                for (int nt = 0; nt < 8; ++nt)
                    MMA16816(acc[mt][nt], a[mt], b[nt]);
        }
    }

    const int g = lane >> 2, t2 = 2 * (lane & 3);
    #pragma unroll
    for (int mt = 0; mt < 2; ++mt) {
        const long r0 = bm + wM * 32 + mt * 16 + g;
        const long r1 = r0 + 8;
        #pragma unroll
        for (int nt = 0; nt < 8; ++nt) {
            const int gcol = (int)bn + wN * 64 + nt * 8 + t2;
            float v00 = acc[mt][nt][0], v01 = acc[mt][nt][1];
            float v10 = acc[mt][nt][2], v11 = acc[mt][nt][3];
            if (bias) {
                const float2 bb = *(const float2*)(bias + gcol);
                v00 += bb.x; v01 += bb.y; v10 += bb.x; v11 += bb.y;
            }
            if (Cf) {
                float2 o0; o0.x = v00; o0.y = v01;
                float2 o1; o1.x = v10; o1.y = v11;
                *(float2*)(Cf + r0 * (long)1024 + gcol) = o0;
                *(float2*)(Cf + r1 * (long)1024 + gcol) = o1;
            }
            if (Ch) {
                *(__half2*)(Ch + r0 * (long)1024 + gcol) =
                    __halves2half2(__float2half(v00), __float2half(v01));
                *(__half2*)(Ch + r1 * (long)1024 + gcol) =
                    __halves2half2(__float2half(v10), __float2half(v11));
            }
        }
    }
}

// ---------------- multi-slice projection GEMM (z selects slice) --------------
// alpha == 1 for all projections (body omits the multiply; x*1.0f == x bitwise,
// omission is still bit-identical).
struct GemmSlice {
    const __half* A; const __half* B; const float* bias;
    float* Cf; __half* Ch;
};
struct Gemm3 { GemmSlice s[3]; };

__global__ void __launch_bounds__(256, 2) mma_gemm_multi(Gemm3 g3)
{
    extern __shared__ char smem[];
    const GemmSlice sl = g3.s[blockIdx.z];
    gemm_body(sl.A, sl.B, sl.bias, sl.Cf, sl.Ch,
              (long)blockIdx.y * 128, (long)blockIdx.x * 128, smem);
}

// ---------------- batched GEMM for the guide block (z = batch) ---------------
// Same structure as R13/R15 winner, alpha applied (guide S uses 1/32).
__global__ void __launch_bounds__(256, 2) mma_gemm(
    const __half* __restrict__ A, const __half* __restrict__ B,
    const float* __restrict__ bias,
    float* __restrict__ Cf, __half* __restrict__ Ch,
    int N, float alpha, long sA, long sB, long sCf, long sCh)
{
    extern __shared__ char smem[];
    const uint32_t sbase = smem_u32(smem);
    const int tid = threadIdx.x, warp = tid >> 5, lane = tid & 31;
    const int wM = warp >> 1, wN = warp & 1;
    const long bm = (long)blockIdx.y * 128, bn = (long)blockIdx.x * 128;
    const int z = blockIdx.z;

    const int lrow = tid >> 1;
    const int lc0 = (tid & 1) * 2;
    const __half* Ag = A + z * sA + (bm + lrow) * (long)KK + lc0 * 8;
    const __half* Bg = B + z * sB + (bn + lrow) * (long)KK + lc0 * 8;
    const uint32_t sw = (uint32_t)((lrow >> 1) & 3);
    const uint32_t soff0 = (uint32_t)lrow * 64 + (((uint32_t)lc0     ^ sw) << 4);
    const uint32_t soff1 = (uint32_t)lrow * 64 + (((uint32_t)(lc0+1) ^ sw) << 4);

    float acc[2][8][4];
    #pragma unroll
    for (int i = 0; i < 2; ++i)
        #pragma unroll
        for (int j = 0; j < 8; ++j)
            #pragma unroll
            for (int k = 0; k < 4; ++k) acc[i][j][k] = 0.f;

    const int NCH = KK / 32;

    #pragma unroll
    for (int s = 0; s < STAGES - 1; ++s) {
        const uint32_t st = sbase + s * STAGE_BYTES;
        CP_ASYNC16(st + soff0,        Ag + (long)s * 32);
        CP_ASYNC16(st + soff1,        Ag + (long)s * 32 + 8);
        CP_ASYNC16(st + 8192 + soff0, Bg + (long)s * 32);
        CP_ASYNC16(st + 8192 + soff1, Bg + (long)s * 32 + 8);
        CP_COMMIT();
    }

    const int l15 = lane & 15;
    const int lk  = lane >> 4;

    for (int c = 0; c < NCH; ++c) {
        CP_WAIT2();
        __syncthreads();

        const int nc = c + STAGES - 1;
        if (nc < NCH) {
            const uint32_t st = sbase + (nc % STAGES) * STAGE_BYTES;
            CP_ASYNC16(st + soff0,        Ag + (long)nc * 32);
            CP_ASYNC16(st + soff1,        Ag + (long)nc * 32 + 8);
            CP_ASYNC16(st + 8192 + soff0, Bg + (long)nc * 32);
            CP_ASYNC16(st + 8192 + soff1, Bg + (long)nc * 32 + 8);
        }
        CP_COMMIT();

        const uint32_t aB = sbase + (c % STAGES) * STAGE_BYTES;
        const uint32_t bB = aB + 8192;
        #pragma unroll
        for (int ks = 0; ks < 2; ++ks) {
            uint32_t a[2][4], b[8][2];
            #pragma unroll
            for (int mt = 0; mt < 2; ++mt) {
                const int row = wM * 32 + mt * 16 + l15;
                const uint32_t kc = (uint32_t)(ks * 2 + lk);
                const uint32_t ad = aB + row * 64 + ((kc ^ ((row >> 1) & 3)) << 4);
                LDSM_X4(a[mt][0], a[mt][1], a[mt][2], a[mt][3], ad);
            }
            #pragma unroll
            for (int p = 0; p < 4; ++p) {
                const int row = wN * 64 + p * 16 + l15;
                const uint32_t kc = (uint32_t)(ks * 2 + lk);
                const uint32_t bd = bB + row * 64 + ((kc ^ ((row >> 1) & 3)) << 4);
                uint32_t r0, r1, r2, r3;
                LDSM_X4(r0, r1, r2, r3, bd);
                b[2 * p][0] = r0; b[2 * p][1] = r2;
                b[2 * p + 1][0] = r1; b[2 * p + 1][1] = r3;
            }
            #pragma unroll
            for (int mt = 0; mt < 2; ++mt)
                #pragma unroll
                for (int nt = 0; nt < 8; ++nt)
                    MMA16816(acc[mt][nt], a[mt], b[nt]);
        }
    }

    const int g = lane >> 2, t2 = 2 * (lane & 3);
    #pragma unroll
    for (int mt = 0; mt < 2; ++mt) {
        const long r0 = bm + wM * 32 + mt * 16 + g;
        const long r1 = r0 + 8;
        #pragma unroll
        for (int nt = 0; nt < 8; ++nt) {
            const int gcol = (int)bn + wN * 64 + nt * 8 + t2;
            float v00 = acc[mt][nt][0] * alpha, v01 = acc[mt][nt][1] * alpha;
            float v10 = acc[mt][nt][2] * alpha, v11 = acc[mt][nt][3] * alpha;
            if (bias) {
                const float2 bb = *(const float2*)(bias + gcol);
                v00 += bb.x; v01 += bb.y; v10 += bb.x; v11 += bb.y;
            }
            if (Cf) {
                float2 o0; o0.x = v00; o0.y = v01;
                float2 o1; o1.x = v10; o1.y = v11;
                *(float2*)(Cf + z * sCf + r0 * (long)N + gcol) = o0;
                *(float2*)(Cf + z * sCf + r1 * (long)N + gcol) = o1;
            }
            if (Ch) {
                *(__half2*)(Ch + z * sCh + r0 * (long)N + gcol) =
                    __halves2half2(__float2half(v00), __float2half(v01));
                *(__half2*)(Ch + z * sCh + r1 * (long)N + gcol) =
                    __halves2half2(__float2half(v10), __float2half(v11));
            }
        }
    }
}

// ---------------- merged f32 -> fp16 conversion: 2 activations ---------------
#define ASEG 4194304L
__global__ void __launch_bounds__(256) convert_a2(
    const float* __restrict__ s0, const float* __restrict__ s1,
    __half* __restrict__ d0, __half* __restrict__ d1)
{
    const long total = 2 * ASEG;
    for (long p = blockIdx.x * (long)blockDim.x + threadIdx.x; p < total;
         p += (long)gridDim.x * blockDim.x) {
        const int w = (int)(p >> 22);
        const long off = p & (ASEG - 1);
        const float* src = w ? s1 : s0;
        __half* dst = w ? d1 : d0;
        float2 x = ((const float2*)src)[off];
        ((__half2*)dst)[off] = __halves2half2(__float2half(x.x), __float2half(x.y));
    }
}

// ---------------- merged f32 -> fp16 conversion for the 5 weights ------------
#define WSEG 524288L
struct CvtW {
    const float *s0, *s1, *s2, *s3, *s4;
    __half *d0, *d1, *d2, *d3, *d4;
};
__global__ void __launch_bounds__(256) convert_w5(CvtW a)
{
    const long total = 5 * WSEG;
    for (long p = blockIdx.x * (long)blockDim.x + threadIdx.x; p < total;
         p += (long)gridDim.x * blockDim.x) {
        const int w = (int)(p >> 19);
        const long off = p & (WSEG - 1);
        const float* src = (w == 0) ? a.s0 : (w == 1) ? a.s1 : (w == 2) ? a.s2
                         : (w == 3) ? a.s3 : a.s4;
        __half* dst = (w == 0) ? a.d0 : (w == 1) ? a.d1 : (w == 2) ? a.d2
                    : (w == 3) ? a.d3 : a.d4;
        float2 x = ((const float2*)src)[off];
        ((__half2*)dst)[off] = __halves2half2(__float2half(x.x), __float2half(x.y));
    }
}

// ---------------- v [B,SK,D] f32 -> vT fp16 [B, D, SK] -----------------------
__global__ void __launch_bounds__(256) transconv_v(
    const float* __restrict__ v, __half* __restrict__ out)
{
    __shared__ float t[32][33];
    const int d0 = blockIdx.x * 32, s0 = blockIdx.y * 32, b = blockIdx.z;
    const int tx = threadIdx.x & 31, ty = threadIdx.x >> 5;
    #pragma unroll
    for (int i = 0; i < 32; i += 8)
        t[ty + i][tx] = v[((long)b * SKL + s0 + ty + i) * DM + d0 + tx];
    __syncthreads();
    #pragma unroll
    for (int i = 0; i < 32; i += 8) {
        const int d = d0 + ty + i, s = s0 + tx;
        out[((long)b * DM + d) * (long)SKL + s] = __float2half(t[tx][ty + i]);
    }
}

// ---------------- block reductions -------------------------------------------
__device__ __forceinline__ float block_reduce_max(float v) {
    __shared__ float sh[8];
    int lane = threadIdx.x & 31, wid = threadIdx.x >> 5;
    #pragma unroll
    for (int o = 16; o; o >>= 1) v = fmaxf(v, __shfl_xor_sync(0xffffffffu, v, o));
    if (lane == 0) sh[wid] = v;
    __syncthreads();
    if (threadIdx.x == 0) {
        float r = sh[0];
        #pragma unroll
        for (int i = 1; i < 8; ++i) r = fmaxf(r, sh[i]);
        sh[0] = r;
    }
    __syncthreads();
    float r = sh[0];
    __syncthreads();
    return r;
}
__device__ __forceinline__ float block_reduce_sum(float v) {
    __shared__ float sh[8];
    int lane = threadIdx.x & 31, wid = threadIdx.x >> 5;
    #pragma unroll
    for (int o = 16; o; o >>= 1) v += __shfl_xor_sync(0xffffffffu, v, o);
    if (lane == 0) sh[wid] = v;
    __syncthreads();
    if (threadIdx.x == 0) {
        float r = sh[0];
        #pragma unroll
        for (int i = 1; i < 8; ++i) r += sh[i];
        sh[0] = r;
    }
    __syncthreads();
    float r = sh[0];
    __syncthreads();
    return r;
}

// ---------------- guide softmax -> fp16 dense (1-pass) -----------------------
__global__ void __launch_bounds__(256) softmax_h(
    const float* __restrict__ x, __half* __restrict__ outh)
{
    x += (long)blockIdx.x * SKL;
    __half2* row = (__half2*)(outh + (long)blockIdx.x * SKL);
    const int tid = threadIdx.x;
    const float4 xv = *(const float4*)(x + tid * 4);
    float lm = fmaxf(fmaxf(xv.x, xv.y), fmaxf(xv.z, xv.w));
    const float m = block_reduce_max(lm);
    float e0 = __expf(xv.x - m), e1 = __expf(xv.y - m);
    float e2 = __expf(xv.z - m), e3 = __expf(xv.w - m);
    const float s = block_reduce_sum(e0 + e1 + e2 + e3);
    const float inv = 1.f / s;
    row[tid * 2]     = __halves2half2(__float2half(e0 * inv), __float2half(e1 * inv));
    row[tid * 2 + 1] = __halves2half2(__float2half(e2 * inv), __float2half(e3 * inv));
}

// ---------------- fused ReLU + LayerNorm -> fp16 hi (+ optional lo) ----------
__global__ void __launch_bounds__(256) relu_ln_split(
    const float* __restrict__ x, const float* __restrict__ g,
    const float* __restrict__ bparm,
    __half* __restrict__ oh, __half* __restrict__ ol)
{
    x  += (long)blockIdx.x * DM;
    oh += (long)blockIdx.x * DM;
    const int tid = threadIdx.x;
    float4 xv = *(const float4*)(x + tid * 4);
    xv.x = fmaxf(xv.x, 0.f); xv.y = fmaxf(xv.y, 0.f);
    xv.z = fmaxf(xv.z, 0.f); xv.w = fmaxf(xv.w, 0.f);
    const float s1 = block_reduce_sum(xv.x + xv.y + xv.z + xv.w);
    const float s2 = block_reduce_sum(xv.x * xv.x + xv.y * xv.y +
                                      xv.z * xv.z + xv.w * xv.w);
    const float mean = s1 / DM;
    const float var  = s2 / DM - mean * mean;
    const float inv  = rsqrtf(var + 1e-5f);
    const float4 gv = *(const float4*)(g + tid * 4);
    const float4 bv = *(const float4*)(bparm + tid * 4);
    float y0 = (xv.x - mean) * inv * gv.x + bv.x;
    float y1 = (xv.y - mean) * inv * gv.y + bv.y;
    float y2 = (xv.z - mean) * inv * gv.z + bv.z;
    float y3 = (xv.w - mean) * inv * gv.w + bv.w;
    __half h0 = __float2half(y0), h1 = __float2half(y1);
    __half h2 = __float2half(y2), h3 = __float2half(y3);
    *(__half2*)(oh + tid * 4)     = __halves2half2(h0, h1);
    *(__half2*)(oh + tid * 4 + 2) = __halves2half2(h2, h3);
    if (ol) {
        ol += (long)blockIdx.x * DM;
        *(__half2*)(ol + tid * 4)     = __halves2half2(
            __float2half(y0 - __half2float(h0)),
            __float2half(y1 - __half2float(h1)));
        *(__half2*)(ol + tid * 4 + 2) = __halves2half2(
            __float2half(y2 - __half2float(h2)),
            __float2half(y3 - __half2float(h3)));
    }
}

// ---------------- tensor-core flash MHA (2 CTA/SM) ---------------------------
// S = QK^T 2-term (Qh,Ql x Kh); PV 1-term (Ph x Vh).
#define MHA_STAGE 16384
#define MHA_SMEM (32768 + 2 * MHA_STAGE)   // 65536
__global__ void __launch_bounds__(256, 2) mha_mma_kernel(
    const __half* __restrict__ qh, const __half* __restrict__ ql,
    const __half* __restrict__ kh,
    const __half* __restrict__ vTh, float* __restrict__ out)
{
    extern __shared__ char smem[];
    const uint32_t sb = smem_u32(smem);
    const uint32_t sQh = sb, sQl = sb + 16384;
    const int tid = threadIdx.x, warp = tid >> 5, lane = tid & 31;
    const int bh = blockIdx.y, b = bh >> 4, h = bh & 15;
    const int q0 = blockIdx.x * 128;

    #pragma unroll
    for (int j = 0; j < 4; ++j) {
        const int idx = tid + j * 256;
        const int r = idx >> 3, c = idx & 7;
        const uint32_t soff = (uint32_t)r * 128 + ((uint32_t)(c ^ (r & 7)) << 4);
        const long gg = ((long)(b * SQL + q0 + r)) * DM + h * DH + c * 8;
        CP_ASYNC16(sQh + soff, qh + gg);
        CP_ASYNC16(sQl + soff, ql + gg);
    }
    auto issue_tile = [&](int t) {
        const uint32_t bufb = sb + 32768 + (uint32_t)(t & 1) * MHA_STAGE;
        #pragma unroll
        for (int j = 0; j < 2; ++j) {
            const int idx = tid + j * 256;
            const int r = idx >> 3, c = idx & 7;
            const uint32_t soff = (uint32_t)r * 128 + ((uint32_t)(c ^ (r & 7)) << 4);
            const long gk = ((long)(b * SKL + t * 64 + r)) * DM + h * DH + c * 8;
            CP_ASYNC16(bufb + soff, kh + gk);
            const long gv = ((long)(b * DM + h * DH + r)) * (long)SKL + t * 64 + c * 8;
            CP_ASYNC16(bufb + 8192 + soff, vTh + gv);
        }
    };
    issue_tile(0);
    CP_COMMIT();

    float oacc[8][4];
    #pragma unroll
    for (int i = 0; i < 8; ++i)
        #pragma unroll
        for (int j = 0; j < 4; ++j) oacc[i][j] = 0.f;
    float mrow[2] = {-1e30f, -1e30f}, lrow[2] = {0.f, 0.f};

    const int l15 = lane & 15, lk = lane >> 4;

    for (int t = 0; t < 16; ++t) {
        if (t + 1 < 16) issue_tile(t + 1);
        CP_COMMIT();
        CP_WAIT1();
        __syncthreads();
        const uint32_t bufb = sb + 32768 + (uint32_t)(t & 1) * MHA_STAGE;

        float sc[8][4];
        #pragma unroll
        for (int i = 0; i < 8; ++i)
            #pragma unroll
            for (int j = 0; j < 4; ++j) sc[i][j] = 0.f;

        #pragma unroll
        for (int ks = 0; ks < 4; ++ks) {
            const int arow = warp * 16 + l15;
            const uint32_t ac = ((uint32_t)((ks * 2 + lk) ^ (arow & 7)) << 4)
                              + (uint32_t)arow * 128;
            uint32_t aH[4], aL[4];
            LDSM_X4(aH[0], aH[1], aH[2], aH[3], sQh + ac);
            LDSM_X4(aL[0], aL[1], aL[2], aL[3], sQl + ac);
            uint32_t bH[8][2];
            #pragma unroll
            for (int p = 0; p < 4; ++p) {
                const int br = p * 16 + l15;
                const uint32_t bc = ((uint32_t)((ks * 2 + lk) ^ (br & 7)) << 4)
                                  + (uint32_t)br * 128;
                uint32_t r0, r1, r2, r3;
                LDSM_X4(r0, r1, r2, r3, bufb + bc);
                bH[2*p][0] = r0; bH[2*p][1] = r2;
                bH[2*p+1][0] = r1; bH[2*p+1][1] = r3;
            }
            #pragma unroll
            for (int nt = 0; nt < 8; ++nt) {
                MMA16816(sc[nt], aH, bH[nt]);
                MMA16816(sc[nt], aL, bH[nt]);
            }
        }

        float mx0 = -1e30f, mx1 = -1e30f;
        #pragma unroll
        for (int nt = 0; nt < 8; ++nt) {
            #pragma unroll
            for (int j = 0; j < 4; ++j) sc[nt][j] *= 0.125f;
            mx0 = fmaxf(mx0, fmaxf(sc[nt][0], sc[nt][1]));
            mx1 = fmaxf(mx1, fmaxf(sc[nt][2], sc[nt][3]));
        }
        mx0 = fmaxf(mx0, __shfl_xor_sync(0xffffffffu, mx0, 1));
        mx0 = fmaxf(mx0, __shfl_xor_sync(0xffffffffu, mx0, 2));
        mx1 = fmaxf(mx1, __shfl_xor_sync(0xffffffffu, mx1, 1));
        mx1 = fmaxf(mx1, __shfl_xor_sync(0xffffffffu, mx1, 2));
        const float mn0 = fmaxf(mrow[0], mx0), mn1 = fmaxf(mrow[1], mx1);
        const float cor0 = __expf(mrow[0] - mn0), cor1 = __expf(mrow[1] - mn1);

        uint32_t pH[8][2];
        float rs0 = 0.f, rs1 = 0.f;
        #pragma unroll
        for (int nt = 0; nt < 8; ++nt) {
            const float p0 = __expf(sc[nt][0] - mn0);
            const float p1 = __expf(sc[nt][1] - mn0);
            const float p2 = __expf(sc[nt][2] - mn1);
            const float p3 = __expf(sc[nt][3] - mn1);
            rs0 += p0 + p1; rs1 += p2 + p3;
            pH[nt][0] = pack_h2(__float2half(p0), __float2half(p1));
            pH[nt][1] = pack_h2(__float2half(p2), __float2half(p3));
        }
        rs0 += __shfl_xor_sync(0xffffffffu, rs0, 1);
        rs0 += __shfl_xor_sync(0xffffffffu, rs0, 2);
        rs1 += __shfl_xor_sync(0xffffffffu, rs1, 1);
        rs1 += __shfl_xor_sync(0xffffffffu, rs1, 2);
        lrow[0] = lrow[0] * cor0 + rs0;
        lrow[1] = lrow[1] * cor1 + rs1;
        mrow[0] = mn0; mrow[1] = mn1;
        #pragma unroll
        for (int nt = 0; nt < 8; ++nt) {
            oacc[nt][0] *= cor0; oacc[nt][1] *= cor0;
            oacc[nt][2] *= cor1; oacc[nt][3] *= cor1;
        }

        #pragma unroll
        for (int ks = 0; ks < 4; ++ks) {
            uint32_t aPh[4] = {pH[2*ks][0], pH[2*ks][1], pH[2*ks+1][0], pH[2*ks+1][1]};
            uint32_t bVh[8][2];
            #pragma unroll
            for (int p = 0; p < 4; ++p) {
                const int br = p * 16 + l15;
                const uint32_t bc = ((uint32_t)((ks * 2 + lk) ^ (br & 7)) << 4)
                                  + (uint32_t)br * 128;
                uint32_t r0, r1, r2, r3;
                LDSM_X4(r0, r1, r2, r3, bufb + 8192 + bc);
                bVh[2*p][0] = r0; bVh[2*p][1] = r2;
                bVh[2*p+1][0] = r1; bVh[2*p+1][1] = r3;
            }
            #pragma unroll
            for (int nt = 0; nt < 8; ++nt)
                MMA16816(oacc[nt], aPh, bVh[nt]);
        }
        __syncthreads();
    }

    const int g = lane >> 2, t2 = 2 * (lane & 3);
    const float inv0 = 1.f / lrow[0], inv1 = 1.f / lrow[1];
    const long qr0 = (long)(b * SQL + q0 + warp * 16 + g);
    #pragma unroll
    for (int nt = 0; nt < 8; ++nt) {
        const int d = h * DH + nt * 8 + t2;
        float2 o0; o0.x = oacc[nt][0] * inv0; o0.y = oacc[nt][1] * inv0;
        float2 o1; o1.x = oacc[nt][2] * inv1; o1.y = oacc[nt][3] * inv1;
        *(float2*)(out + qr0 * DM + d) = o0;
        *(float2*)(out + (qr0 + 8) * DM + d) = o1;
    }
}

// ---------------- launch -----------------------------------------------------
extern "C" void kernel_launch(void* const* d_in, const int* in_sizes, int n_in,
                              void* d_out, int out_size)
{
    const float* hs   = (const float*)d_in[0];
    const float* ctx  = (const float*)d_in[1];
    const float* Wq   = (const float*)d_in[2];
    const float* bq   = (const float*)d_in[3];
    const float* Wk   = (const float*)d_in[4];
    const float* bk   = (const float*)d_in[5];
    const float* Wv   = (const float*)d_in[6];
    const float* bv   = (const float*)d_in[7];
    const float* Wobs = (const float*)d_in[8];
    const float* bobs = (const float*)d_in[9];
    const float* Wmat = (const float*)d_in[10];
    const float* bmat = (const float*)d_in[11];
    const float* lng  = (const float*)d_in[12];
    const float* lnb  = (const float*)d_in[13];
    float* out = (float*)d_out;

    float *pv, *ps, *pnq, *pnk;
    __half *hsh, *ctxh, *qh, *kh, *vTh, *ph, *gh;
    __half *Wqh, *Wkh, *Wvh, *Woh, *Wmh;
    __half *mqh, *mql, *mkh;
    cudaGetSymbolAddress((void**)&pv,   g_v);
    cudaGetSymbolAddress((void**)&ps,   g_s);
    cudaGetSymbolAddress((void**)&pnq,  g_newq);
    cudaGetSymbolAddress((void**)&pnk,  g_newk);
    cudaGetSymbolAddress((void**)&hsh,  g_hsh);
    cudaGetSymbolAddress((void**)&ctxh, g_ctxh);
    cudaGetSymbolAddress((void**)&qh,   g_qh);
    cudaGetSymbolAddress((void**)&kh,   g_kh);
    cudaGetSymbolAddress((void**)&vTh,  g_vTh);
    cudaGetSymbolAddress((void**)&ph,   g_ph);
    cudaGetSymbolAddress((void**)&gh,   g_gh);
    cudaGetSymbolAddress((void**)&Wqh,  g_Wqh);
    cudaGetSymbolAddress((void**)&Wkh,  g_Wkh);
    cudaGetSymbolAddress((void**)&Wvh,  g_Wvh);
    cudaGetSymbolAddress((void**)&Woh,  g_Woh);
    cudaGetSymbolAddress((void**)&Wmh,  g_Wmh);
    cudaGetSymbolAddress((void**)&mqh,  g_mqh);
    cudaGetSymbolAddress((void**)&mql,  g_mql);
    cudaGetSymbolAddress((void**)&mkh,  g_mkh);

    cudaFuncSetAttribute(mma_gemm, cudaFuncAttributeMaxDynamicSharedMemorySize,
                         GEMM_SMEM);
    cudaFuncSetAttribute(mma_gemm_multi, cudaFuncAttributeMaxDynamicSharedMemorySize,
                         GEMM_SMEM);
    cudaFuncSetAttribute(mha_mma_kernel, cudaFuncAttributeMaxDynamicSharedMemorySize,
                         MHA_SMEM);

    const dim3 T(256);
    const dim3 gBat(8, 8, 8);        // N=1024, M=1024, batch 8
    const long sQ = 1024L * 1024;    // per-batch stride (dense 1024-wide)

    // input conversions
    convert_a2<<<2368, T>>>(hs, ctx, hsh, ctxh);
    CvtW cw;
    cw.s0 = Wq;   cw.d0 = Wqh;
    cw.s1 = Wk;   cw.d1 = Wkh;
    cw.s2 = Wv;   cw.d2 = Wvh;
    cw.s3 = Wobs; cw.d3 = Woh;
    cw.s4 = Wmat; cw.d4 = Wmh;
    convert_w5<<<1480, T>>>(cw);

    // q, k, v projections in ONE launch (z selects slice)
    Gemm3 gq;
    gq.s[0] = { hsh,  Wqh, bq, nullptr, qh };
    gq.s[1] = { ctxh, Wkh, bk, nullptr, kh };
    gq.s[2] = { ctxh, Wvh, bv, pv, nullptr };
    mma_gemm_multi<<<dim3(8, 64, 3), T, GEMM_SMEM>>>(gq);
    transconv_v<<<dim3(32, 32, 8), T>>>(pv, vTh);

    // guide block: S = q_hi @ k_hi^T / 32, softmax, P_hi @ V_hi
    mma_gemm<<<gBat, T, GEMM_SMEM>>>(qh, kh, nullptr, ps, nullptr,
                                     1024, 0.03125f, sQ, sQ, sQ, 0);
    softmax_h<<<BB * SQL, T>>>(ps, ph);
    mma_gemm<<<gBat, T, GEMM_SMEM>>>(ph, vTh, nullptr, nullptr, gh,
                                     1024, 1.f, sQ, sQ, 0, sQ);

    // obs + mat projections in ONE launch
    Gemm3 gm;
    gm.s[0] = { gh, Woh, bobs, pnq, nullptr };
    gm.s[1] = { kh, Wmh, bmat, pnk, nullptr };
    gm.s[2] = { nullptr, nullptr, nullptr, nullptr, nullptr };
    mma_gemm_multi<<<dim3(8, 64, 2), T, GEMM_SMEM>>>(gm);
    relu_ln_split<<<BB * SQL, T>>>(pnq, lng, lnb, mqh, mql);
    relu_ln_split<<<BB * SKL, T>>>(pnk, lng, lnb, mkh, nullptr);

    // tensor-core multi-head attention (2 CTA/SM)
    mha_mma_kernel<<<dim3(SQL / 128, BB * NH), T, MHA_SMEM>>>(
        mqh, mql, mkh, vTh, out);
}

// round 17
// speedup vs baseline: 1.6119x; 1.0008x over previous
#include <cuda_runtime.h>
#include <cuda_fp16.h>
#include <math.h>
#include <stdint.h>

#define BB 8
#define SQL 1024
#define SKL 1024
#define DM  1024
#define NH  16
#define DH  64

// ---------------- scratch (static device arrays; no cudaMalloc) -------------
__device__ float g_v   [BB*SKL*DM];
__device__ float g_s   [(long)BB*SQL*SKL];
__device__ float g_newq[BB*SQL*DM];
__device__ float g_newk[BB*SKL*DM];

__device__ __half g_hsh [8192L*1024];
__device__ __half g_ctxh[8192L*1024];
__device__ __half g_qh  [8192L*1024];
__device__ __half g_kh  [8192L*1024];
__device__ __half g_vTh [8192L*1024];
__device__ __half g_ph  [8192L*1024];
__device__ __half g_gh  [8192L*1024];
__device__ __half g_Wqh [1024L*1024];
__device__ __half g_Wkh [1024L*1024];
__device__ __half g_Wvh [1024L*1024];
__device__ __half g_Woh [1024L*1024];
__device__ __half g_Wmh [1024L*1024];
// LayerNorm outputs for MHA
__device__ __half g_mqh[8192L*1024];
__device__ __half g_mql[8192L*1024];
__device__ __half g_mkh[8192L*1024];

// ---------------- helpers ----------------------------------------------------
__device__ __forceinline__ uint32_t smem_u32(const void* p) {
    uint32_t a;
    asm("{ .reg .u64 t; cvta.to.shared.u64 t, %1; cvt.u32.u64 %0, t; }"
        : "=r"(a) : "l"(p));
    return a;
}
#define CP_ASYNC16(sa, ga) \
    asm volatile("cp.async.cg.shared.global [%0], [%1], 16;" :: "r"(sa), "l"(ga))
#define CP_COMMIT() asm volatile("cp.async.commit_group;" ::: "memory")
#define CP_WAIT1()  asm volatile("cp.async.wait_group 1;" ::: "memory")
#define CP_WAIT2()  asm volatile("cp.async.wait_group 2;" ::: "memory")

#define LDSM_X4(r0, r1, r2, r3, a) \
    asm volatile("ldmatrix.sync.aligned.m8n8.x4.shared.b16 {%0,%1,%2,%3}, [%4];" \
        : "=r"(r0), "=r"(r1), "=r"(r2), "=r"(r3) : "r"(a))

#define MMA16816(c, a, b) \
    asm volatile("mma.sync.aligned.m16n8k16.row.col.f32.f16.f16.f32 " \
        "{%0,%1,%2,%3}, {%4,%5,%6,%7}, {%8,%9}, {%0,%1,%2,%3};" \
        : "+f"((c)[0]), "+f"((c)[1]), "+f"((c)[2]), "+f"((c)[3]) \
        : "r"((a)[0]), "r"((a)[1]), "r"((a)[2]), "r"((a)[3]), \
          "r"((b)[0]), "r"((b)[1]))

__device__ __forceinline__ uint32_t pack_h2(__half a, __half b) {
    __half2 t = __halves2half2(a, b);
    return *(uint32_t*)&t;
}

#define STAGES 4
#define STAGE_BYTES 16384
#define GEMM_SMEM (STAGES * STAGE_BYTES)   // 65536
#define KK 1024

// ---------------- shared GEMM body (128x128 tile, K=1024, 4-stage) -----------
__device__ __forceinline__ void gemm_body(
    const __half* __restrict__ A, const __half* __restrict__ B,
    const float* __restrict__ bias,
    float* __restrict__ Cf, __half* __restrict__ Ch,
    long bm, long bn, char* smem)
{
    const uint32_t sbase = smem_u32(smem);
    const int tid = threadIdx.x, warp = tid >> 5, lane = tid & 31;
    const int wM = warp >> 1, wN = warp & 1;

    const int lrow = tid >> 1;
    const int lc0 = (tid & 1) * 2;
    const __half* Ag = A + (bm + lrow) * (long)KK + lc0 * 8;
    const __half* Bg = B + (bn + lrow) * (long)KK + lc0 * 8;
    const uint32_t sw = (uint32_t)((lrow >> 1) & 3);
    const uint32_t soff0 = (uint32_t)lrow * 64 + (((uint32_t)lc0     ^ sw) << 4);
    const uint32_t soff1 = (uint32_t)lrow * 64 + (((uint32_t)(lc0+1) ^ sw) << 4);

    float acc[2][8][4];
    #pragma unroll
    for (int i = 0; i < 2; ++i)
        #pragma unroll
        for (int j = 0; j < 8; ++j)
            #pragma unroll
            for (int k = 0; k < 4; ++k) acc[i][j][k] = 0.f;

    const int NCH = KK / 32;

    #pragma unroll
    for (int s = 0; s < STAGES - 1; ++s) {
        const uint32_t st = sbase + s * STAGE_BYTES;
        CP_ASYNC16(st + soff0,        Ag + (long)s * 32);
        CP_ASYNC16(st + soff1,        Ag + (long)s * 32 + 8);
        CP_ASYNC16(st + 8192 + soff0, Bg + (long)s * 32);
        CP_ASYNC16(st + 8192 + soff1, Bg + (long)s * 32 + 8);
        CP_COMMIT();
    }

    const int l15 = lane & 15;
    const int lk  = lane >> 4;

    for (int c = 0; c < NCH; ++c) {
        CP_WAIT2();
        __syncthreads();

        const int nc = c + STAGES - 1;
        if (nc < NCH) {
            const uint32_t st = sbase + (nc % STAGES) * STAGE_BYTES;
            CP_ASYNC16(st + soff0,        Ag + (long)nc * 32);
            CP_ASYNC16(st + soff1,        Ag + (long)nc * 32 + 8);
            CP_ASYNC16(st + 8192 + soff0, Bg + (long)nc * 32);
            CP_ASYNC16(st + 8192 + soff1, Bg + (long)nc * 32 + 8);
        }
        CP_COMMIT();

        const uint32_t aB = sbase + (c % STAGES) * STAGE_BYTES;
        const uint32_t bB = aB + 8192;
        #pragma unroll
        for (int ks = 0; ks < 2; ++ks) {
            uint32_t a[2][4], b[8][2];
            #pragma unroll
            for (int mt = 0; mt < 2; ++mt) {
                const int row = wM * 32 + mt * 16 + l15;
                const uint32_t kc = (uint32_t)(ks * 2 + lk);
                const uint32_t ad = aB + row * 64 + ((kc ^ ((row >> 1) & 3)) << 4);
                LDSM_X4(a[mt][0], a[mt][1], a[mt][2], a[mt][3], ad);
            }
            #pragma unroll
            for (int p = 0; p < 4; ++p) {
                const int row = wN * 64 + p * 16 + l15;
                const uint32_t kc = (uint32_t)(ks * 2 + lk);
                const uint32_t bd = bB + row * 64 + ((kc ^ ((row >> 1) & 3)) << 4);
                uint32_t r0, r1, r2, r3;
                LDSM_X4(r0, r1, r2, r3, bd);
                b[2 * p][0] = r0; b[2 * p][1] = r2;
                b[2 * p + 1][0] = r1; b[2 * p + 1][1] = r3;
            }
            #pragma unroll
            for (int mt = 0; mt < 2; ++mt)
                #pragma unroll
                for (int nt = 0; nt < 8; ++nt)
                    MMA16816(acc[mt][nt], a[mt], b[nt]);
        }
    }

    const int g = lane >> 2, t2 = 2 * (lane & 3);
    #pragma unroll
    for (int mt = 0; mt < 2; ++mt) {
        const long r0 = bm + wM * 32 + mt * 16 + g;
        const long r1 = r0 + 8;
        #pragma unroll
        for (int nt = 0; nt < 8; ++nt) {
            const int gcol = (int)bn + wN * 64 + nt * 8 + t2;
            float v00 = acc[mt][nt][0], v01 = acc[mt][nt][1];
            float v10 = acc[mt][nt][2], v11 = acc[mt][nt][3];
            if (bias) {
                const float2 bb = *(const float2*)(bias + gcol);
                v00 += bb.x; v01 += bb.y; v10 += bb.x; v11 += bb.y;
            }
            if (Cf) {
                float2 o0; o0.x = v00; o0.y = v01;
                float2 o1; o1.x = v10; o1.y = v11;
                *(float2*)(Cf + r0 * (long)1024 + gcol) = o0;
                *(float2*)(Cf + r1 * (long)1024 + gcol) = o1;
            }
            if (Ch) {
                *(__half2*)(Ch + r0 * (long)1024 + gcol) =
                    __halves2half2(__float2half(v00), __float2half(v01));
                *(__half2*)(Ch + r1 * (long)1024 + gcol) =
                    __halves2half2(__float2half(v10), __float2half(v11));
            }
        }
    }
}

// ---------------- multi-slice projection GEMM (z selects slice) --------------
struct GemmSlice {
    const __half* A; const __half* B; const float* bias;
    float* Cf; __half* Ch;
};
struct Gemm3 { GemmSlice s[3]; };

__global__ void __launch_bounds__(256, 2) mma_gemm_multi(Gemm3 g3)
{
    extern __shared__ char smem[];
    const GemmSlice sl = g3.s[blockIdx.z];
    gemm_body(sl.A, sl.B, sl.bias, sl.Cf, sl.Ch,
              (long)blockIdx.y * 128, (long)blockIdx.x * 128, smem);
}

// ---------------- merged guide-S + mat projection ----------------------------
// grid (8, 128): yy < 64 -> guide S batch yy>>3, tile yy&7 (alpha 1/32, no bias);
//                yy >= 64 -> mat projection tile (yy-64) (alpha 1, bias bmat).
// Both write f32 only; epilogue applies v*alpha then optional bias — bitwise
// identical to the separate kernels (x*1.0f == x).
__global__ void __launch_bounds__(256, 2) mma_gemm_smat(
    const __half* __restrict__ qh, const __half* __restrict__ khS,
    float* __restrict__ ps,
    const __half* __restrict__ khA, const __half* __restrict__ Wmh,
    const float* __restrict__ bmat, float* __restrict__ pnk)
{
    extern __shared__ char smem[];
    const uint32_t sbase = smem_u32(smem);
    const int tid = threadIdx.x, warp = tid >> 5, lane = tid & 31;
    const int wM = warp >> 1, wN = warp & 1;
    const long bn = (long)blockIdx.x * 128;
    const int yy = blockIdx.y;

    const __half* Abase; const __half* Bbase; const float* bias;
    float* Cf; float alpha; long bm;
    if (yy < 64) {
        const long z = yy >> 3;
        Abase = qh + z * (1024L * 1024);
        Bbase = khS + z * (1024L * 1024);
        bias = nullptr;
        Cf = ps + z * (1024L * 1024);
        alpha = 0.03125f;
        bm = (long)(yy & 7) * 128;
    } else {
        Abase = khA; Bbase = Wmh;
        bias = bmat; Cf = pnk;
        alpha = 1.0f;
        bm = (long)(yy - 64) * 128;
    }

    const int lrow = tid >> 1;
    const int lc0 = (tid & 1) * 2;
    const __half* Ag = Abase + (bm + lrow) * (long)KK + lc0 * 8;
    const __half* Bg = Bbase + (bn + lrow) * (long)KK + lc0 * 8;
    const uint32_t sw = (uint32_t)((lrow >> 1) & 3);
    const uint32_t soff0 = (uint32_t)lrow * 64 + (((uint32_t)lc0     ^ sw) << 4);
    const uint32_t soff1 = (uint32_t)lrow * 64 + (((uint32_t)(lc0+1) ^ sw) << 4);

    float acc[2][8][4];
    #pragma unroll
    for (int i = 0; i < 2; ++i)
        #pragma unroll
        for (int j = 0; j < 8; ++j)
            #pragma unroll
            for (int k = 0; k < 4; ++k) acc[i][j][k] = 0.f;

    const int NCH = KK / 32;

    #pragma unroll
    for (int s = 0; s < STAGES - 1; ++s) {
        const uint32_t st = sbase + s * STAGE_BYTES;
        CP_ASYNC16(st + soff0,        Ag + (long)s * 32);
        CP_ASYNC16(st + soff1,        Ag + (long)s * 32 + 8);
        CP_ASYNC16(st + 8192 + soff0, Bg + (long)s * 32);
        CP_ASYNC16(st + 8192 + soff1, Bg + (long)s * 32 + 8);
        CP_COMMIT();
    }

    const int l15 = lane & 15;
    const int lk  = lane >> 4;

    for (int c = 0; c < NCH; ++c) {
        CP_WAIT2();
        __syncthreads();

        const int nc = c + STAGES - 1;
        if (nc < NCH) {
            const uint32_t st = sbase + (nc % STAGES) * STAGE_BYTES;
            CP_ASYNC16(st + soff0,        Ag + (long)nc * 32);
            CP_ASYNC16(st + soff1,        Ag + (long)nc * 32 + 8);
            CP_ASYNC16(st + 8192 + soff0, Bg + (long)nc * 32);
            CP_ASYNC16(st + 8192 + soff1, Bg + (long)nc * 32 + 8);
        }
        CP_COMMIT();

        const uint32_t aB = sbase + (c % STAGES) * STAGE_BYTES;
        const uint32_t bB = aB + 8192;
        #pragma unroll
        for (int ks = 0; ks < 2; ++ks) {
            uint32_t a[2][4], b[8][2];
            #pragma unroll
            for (int mt = 0; mt < 2; ++mt) {
                const int row = wM * 32 + mt * 16 + l15;
                const uint32_t kc = (uint32_t)(ks * 2 + lk);
                const uint32_t ad = aB + row * 64 + ((kc ^ ((row >> 1) & 3)) << 4);
                LDSM_X4(a[mt][0], a[mt][1], a[mt][2], a[mt][3], ad);
            }
            #pragma unroll
            for (int p = 0; p < 4; ++p) {
                const int row = wN * 64 + p * 16 + l15;
                const uint32_t kc = (uint32_t)(ks * 2 + lk);
                const uint32_t bd = bB + row * 64 + ((kc ^ ((row >> 1) & 3)) << 4);
                uint32_t r0, r1, r2, r3;
                LDSM_X4(r0, r1, r2, r3, bd);
                b[2 * p][0] = r0; b[2 * p][1] = r2;
                b[2 * p + 1][0] = r1; b[2 * p + 1][1] = r3;
            }
            #pragma unroll
            for (int mt = 0; mt < 2; ++mt)
                #pragma unroll
                for (int nt = 0; nt < 8; ++nt)
                    MMA16816(acc[mt][nt], a[mt], b[nt]);
        }
    }

    const int g = lane >> 2, t2 = 2 * (lane & 3);
    #pragma unroll
    for (int mt = 0; mt < 2; ++mt) {
        const long r0 = bm + wM * 32 + mt * 16 + g;
        const long r1 = r0 + 8;
        #pragma unroll
        for (int nt = 0; nt < 8; ++nt) {
            const int gcol = (int)bn + wN * 64 + nt * 8 + t2;
            float v00 = acc[mt][nt][0] * alpha, v01 = acc[mt][nt][1] * alpha;
            float v10 = acc[mt][nt][2] * alpha, v11 = acc[mt][nt][3] * alpha;
            if (bias) {
                const float2 bb = *(const float2*)(bias + gcol);
                v00 += bb.x; v01 += bb.y; v10 += bb.x; v11 += bb.y;
            }
            float2 o0; o0.x = v00; o0.y = v01;
            float2 o1; o1.x = v10; o1.y = v11;
            *(float2*)(Cf + r0 * (long)1024 + gcol) = o0;
            *(float2*)(Cf + r1 * (long)1024 + gcol) = o1;
        }
    }
}

// ---------------- batched GEMM (guide PV; z = batch) -------------------------
__global__ void __launch_bounds__(256, 2) mma_gemm(
    const __half* __restrict__ A, const __half* __restrict__ B,
    const float* __restrict__ bias,
    float* __restrict__ Cf, __half* __restrict__ Ch,
    int N, float alpha, long sA, long sB, long sCf, long sCh)
{
    extern __shared__ char smem[];
    const uint32_t sbase = smem_u32(smem);
    const int tid = threadIdx.x, warp = tid >> 5, lane = tid & 31;
    const int wM = warp >> 1, wN = warp & 1;
    const long bm = (long)blockIdx.y * 128, bn = (long)blockIdx.x * 128;
    const int z = blockIdx.z;

    const int lrow = tid >> 1;
    const int lc0 = (tid & 1) * 2;
    const __half* Ag = A + z * sA + (bm + lrow) * (long)KK + lc0 * 8;
    const __half* Bg = B + z * sB + (bn + lrow) * (long)KK + lc0 * 8;
    const uint32_t sw = (uint32_t)((lrow >> 1) & 3);
    const uint32_t soff0 = (uint32_t)lrow * 64 + (((uint32_t)lc0     ^ sw) << 4);
    const uint32_t soff1 = (uint32_t)lrow * 64 + (((uint32_t)(lc0+1) ^ sw) << 4);

    float acc[2][8][4];
    #pragma unroll
    for (int i = 0; i < 2; ++i)
        #pragma unroll
        for (int j = 0; j < 8; ++j)
            #pragma unroll
            for (int k = 0; k < 4; ++k) acc[i][j][k] = 0.f;

    const int NCH = KK / 32;

    #pragma unroll
    for (int s = 0; s < STAGES - 1; ++s) {
        const uint32_t st = sbase + s * STAGE_BYTES;
        CP_ASYNC16(st + soff0,        Ag + (long)s * 32);
        CP_ASYNC16(st + soff1,        Ag + (long)s * 32 + 8);
        CP_ASYNC16(st + 8192 + soff0, Bg + (long)s * 32);
        CP_ASYNC16(st + 8192 + soff1, Bg + (long)s * 32 + 8);
        CP_COMMIT();
    }

    const int l15 = lane & 15;
    const int lk  = lane >> 4;

    for (int c = 0; c < NCH; ++c) {
        CP_WAIT2();
        __syncthreads();

        const int nc = c + STAGES - 1;
        if (nc < NCH) {
            const uint32_t st = sbase + (nc % STAGES) * STAGE_BYTES;
            CP_ASYNC16(st + soff0,        Ag + (long)nc * 32);
            CP_ASYNC16(st + soff1,        Ag + (long)nc * 32 + 8);
            CP_ASYNC16(st + 8192 + soff0, Bg + (long)nc * 32);
            CP_ASYNC16(st + 8192 + soff1, Bg + (long)nc * 32 + 8);
        }
        CP_COMMIT();

        const uint32_t aB = sbase + (c % STAGES) * STAGE_BYTES;
        const uint32_t bB = aB + 8192;
        #pragma unroll
        for (int ks = 0; ks < 2; ++ks) {
            uint32_t a[2][4], b[8][2];
            #pragma unroll
            for (int mt = 0; mt < 2; ++mt) {
                const int row = wM * 32 + mt * 16 + l15;
                const uint32_t kc = (uint32_t)(ks * 2 + lk);
                const uint32_t ad = aB + row * 64 + ((kc ^ ((row >> 1) & 3)) << 4);
                LDSM_X4(a[mt][0], a[mt][1], a[mt][2], a[mt][3], ad);
            }
            #pragma unroll
            for (int p = 0; p < 4; ++p) {
                const int row = wN * 64 + p * 16 + l15;
                const uint32_t kc = (uint32_t)(ks * 2 + lk);
                const uint32_t bd = bB + row * 64 + ((kc ^ ((row >> 1) & 3)) << 4);
                uint32_t r0, r1, r2, r3;
                LDSM_X4(r0, r1, r2, r3, bd);
                b[2 * p][0] = r0; b[2 * p][1] = r2;
                b[2 * p + 1][0] = r1; b[2 * p + 1][1] = r3;
            }
            #pragma unroll
            for (int mt = 0; mt < 2; ++mt)
                #pragma unroll
                for (int nt = 0; nt < 8; ++nt)
                    MMA16816(acc[mt][nt], a[mt], b[nt]);
        }
    }

    const int g = lane >> 2, t2 = 2 * (lane & 3);
    #pragma unroll
    for (int mt = 0; mt < 2; ++mt) {
        const long r0 = bm + wM * 32 + mt * 16 + g;
        const long r1 = r0 + 8;
        #pragma unroll
        for (int nt = 0; nt < 8; ++nt) {
            const int gcol = (int)bn + wN * 64 + nt * 8 + t2;
            float v00 = acc[mt][nt][0] * alpha, v01 = acc[mt][nt][1] * alpha;
            float v10 = acc[mt][nt][2] * alpha, v11 = acc[mt][nt][3] * alpha;
            if (bias) {
                const float2 bb = *(const float2*)(bias + gcol);
                v00 += bb.x; v01 += bb.y; v10 += bb.x; v11 += bb.y;
            }
            if (Cf) {
                float2 o0; o0.x = v00; o0.y = v01;
                float2 o1; o1.x = v10; o1.y = v11;
                *(float2*)(Cf + z * sCf + r0 * (long)N + gcol) = o0;
                *(float2*)(Cf + z * sCf + r1 * (long)N + gcol) = o1;
            }
            if (Ch) {
                *(__half2*)(Ch + z * sCh + r0 * (long)N + gcol) =
                    __halves2half2(__float2half(v00), __float2half(v01));
                *(__half2*)(Ch + z * sCh + r1 * (long)N + gcol) =
                    __halves2half2(__float2half(v10), __float2half(v11));
            }
        }
    }
}

// ---------------- merged f32 -> fp16 conversion: 2 activations ---------------
#define ASEG 4194304L
__global__ void __launch_bounds__(256) convert_a2(
    const float* __restrict__ s0, const float* __restrict__ s1,
    __half* __restrict__ d0, __half* __restrict__ d1)
{
    const long total = 2 * ASEG;
    for (long p = blockIdx.x * (long)blockDim.x + threadIdx.x; p < total;
         p += (long)gridDim.x * blockDim.x) {
        const int w = (int)(p >> 22);
        const long off = p & (ASEG - 1);
        const float* src = w ? s1 : s0;
        __half* dst = w ? d1 : d0;
        float2 x = ((const float2*)src)[off];
        ((__half2*)dst)[off] = __halves2half2(__float2half(x.x), __float2half(x.y));
    }
}

// ---------------- merged f32 -> fp16 conversion for the 5 weights ------------
#define WSEG 524288L
struct CvtW {
    const float *s0, *s1, *s2, *s3, *s4;
    __half *d0, *d1, *d2, *d3, *d4;
};
__global__ void __launch_bounds__(256) convert_w5(CvtW a)
{
    const long total = 5 * WSEG;
    for (long p = blockIdx.x * (long)blockDim.x + threadIdx.x; p < total;
         p += (long)gridDim.x * blockDim.x) {
        const int w = (int)(p >> 19);
        const long off = p & (WSEG - 1);
        const float* src = (w == 0) ? a.s0 : (w == 1) ? a.s1 : (w == 2) ? a.s2
                         : (w == 3) ? a.s3 : a.s4;
        __half* dst = (w == 0) ? a.d0 : (w == 1) ? a.d1 : (w == 2) ? a.d2
                    : (w == 3) ? a.d3 : a.d4;
        float2 x = ((const float2*)src)[off];
        ((__half2*)dst)[off] = __halves2half2(__float2half(x.x), __float2half(x.y));
    }
}

// ---------------- v [B,SK,D] f32 -> vT fp16 [B, D, SK] -----------------------
__global__ void __launch_bounds__(256) transconv_v(
    const float* __restrict__ v, __half* __restrict__ out)
{
    __shared__ float t[32][33];
    const int d0 = blockIdx.x * 32, s0 = blockIdx.y * 32, b = blockIdx.z;
    const int tx = threadIdx.x & 31, ty = threadIdx.x >> 5;
    #pragma unroll
    for (int i = 0; i < 32; i += 8)
        t[ty + i][tx] = v[((long)b * SKL + s0 + ty + i) * DM + d0 + tx];
    __syncthreads();
    #pragma unroll
    for (int i = 0; i < 32; i += 8) {
        const int d = d0 + ty + i, s = s0 + tx;
        out[((long)b * DM + d) * (long)SKL + s] = __float2half(t[tx][ty + i]);
    }
}

// ---------------- block reductions -------------------------------------------
__device__ __forceinline__ float block_reduce_max(float v) {
    __shared__ float sh[8];
    int lane = threadIdx.x & 31, wid = threadIdx.x >> 5;
    #pragma unroll
    for (int o = 16; o; o >>= 1) v = fmaxf(v, __shfl_xor_sync(0xffffffffu, v, o));
    if (lane == 0) sh[wid] = v;
    __syncthreads();
    if (threadIdx.x == 0) {
        float r = sh[0];
        #pragma unroll
        for (int i = 1; i < 8; ++i) r = fmaxf(r, sh[i]);
        sh[0] = r;
    }
    __syncthreads();
    float r = sh[0];
    __syncthreads();
    return r;
}
__device__ __forceinline__ float block_reduce_sum(float v) {
    __shared__ float sh[8];
    int lane = threadIdx.x & 31, wid = threadIdx.x >> 5;
    #pragma unroll
    for (int o = 16; o; o >>= 1) v += __shfl_xor_sync(0xffffffffu, v, o);
    if (lane == 0) sh[wid] = v;
    __syncthreads();
    if (threadIdx.x == 0) {
        float r = sh[0];
        #pragma unroll
        for (int i = 1; i < 8; ++i) r += sh[i];
        sh[0] = r;
    }
    __syncthreads();
    float r = sh[0];
    __syncthreads();
    return r;
}

// ---------------- guide softmax -> fp16 dense (1-pass) -----------------------
__global__ void __launch_bounds__(256) softmax_h(
    const float* __restrict__ x, __half* __restrict__ outh)
{
    x += (long)blockIdx.x * SKL;
    __half2* row = (__half2*)(outh + (long)blockIdx.x * SKL);
    const int tid = threadIdx.x;
    const float4 xv = *(const float4*)(x + tid * 4);
    float lm = fmaxf(fmaxf(xv.x, xv.y), fmaxf(xv.z, xv.w));
    const float m = block_reduce_max(lm);
    float e0 = __expf(xv.x - m), e1 = __expf(xv.y - m);
    float e2 = __expf(xv.z - m), e3 = __expf(xv.w - m);
    const float s = block_reduce_sum(e0 + e1 + e2 + e3);
    const float inv = 1.f / s;
    row[tid * 2]     = __halves2half2(__float2half(e0 * inv), __float2half(e1 * inv));
    row[tid * 2 + 1] = __halves2half2(__float2half(e2 * inv), __float2half(e3 * inv));
}

// ---------------- merged fused ReLU + LayerNorm ------------------------------
// blocks [0, 8192): pnq row -> mqh + mql;  [8192, 16384): pnk row -> mkh only.
// Per-row math identical to the separate launches (bit-identical outputs).
__global__ void __launch_bounds__(256) relu_ln_merged(
    const float* __restrict__ xq, const float* __restrict__ xk,
    const float* __restrict__ g, const float* __restrict__ bparm,
    __half* __restrict__ oqh, __half* __restrict__ oql,
    __half* __restrict__ okh)
{
    const int bid = blockIdx.x;
    const bool isQ = bid < 8192;
    const long row = isQ ? bid : (bid - 8192);
    const float* x = (isQ ? xq : xk) + row * DM;
    __half* oh = (isQ ? oqh : okh) + row * DM;
    __half* ol = isQ ? (oql + row * DM) : nullptr;

    const int tid = threadIdx.x;
    float4 xv = *(const float4*)(x + tid * 4);
    xv.x = fmaxf(xv.x, 0.f); xv.y = fmaxf(xv.y, 0.f);
    xv.z = fmaxf(xv.z, 0.f); xv.w = fmaxf(xv.w, 0.f);
    const float s1 = block_reduce_sum(xv.x + xv.y + xv.z + xv.w);
    const float s2 = block_reduce_sum(xv.x * xv.x + xv.y * xv.y +
                                      xv.z * xv.z + xv.w * xv.w);
    const float mean = s1 / DM;
    const float var  = s2 / DM - mean * mean;
    const float inv  = rsqrtf(var + 1e-5f);
    const float4 gv = *(const float4*)(g + tid * 4);
    const float4 bv = *(const float4*)(bparm + tid * 4);
    float y0 = (xv.x - mean) * inv * gv.x + bv.x;
    float y1 = (xv.y - mean) * inv * gv.y + bv.y;
    float y2 = (xv.z - mean) * inv * gv.z + bv.z;
    float y3 = (xv.w - mean) * inv * gv.w + bv.w;
    __half h0 = __float2half(y0), h1 = __float2half(y1);
    __half h2 = __float2half(y2), h3 = __float2half(y3);
    *(__half2*)(oh + tid * 4)     = __halves2half2(h0, h1);
    *(__half2*)(oh + tid * 4 + 2) = __halves2half2(h2, h3);
    if (ol) {
        *(__half2*)(ol + tid * 4)     = __halves2half2(
            __float2half(y0 - __half2float(h0)),
            __float2half(y1 - __half2float(h1)));
        *(__half2*)(ol + tid * 4 + 2) = __halves2half2(
            __float2half(y2 - __half2float(h2)),
            __float2half(y3 - __half2float(h3)));
    }
}

// ---------------- tensor-core flash MHA (2 CTA/SM) ---------------------------
#define MHA_STAGE 16384
#define MHA_SMEM (32768 + 2 * MHA_STAGE)   // 65536
__global__ void __launch_bounds__(256, 2) mha_mma_kernel(
    const __half* __restrict__ qh, const __half* __restrict__ ql,
    const __half* __restrict__ kh,
    const __half* __restrict__ vTh, float* __restrict__ out)
{
    extern __shared__ char smem[];
    const uint32_t sb = smem_u32(smem);
    const uint32_t sQh = sb, sQl = sb + 16384;
    const int tid = threadIdx.x, warp = tid >> 5, lane = tid & 31;
    const int bh = blockIdx.y, b = bh >> 4, h = bh & 15;
    const int q0 = blockIdx.x * 128;

    #pragma unroll
    for (int j = 0; j < 4; ++j) {
        const int idx = tid + j * 256;
        const int r = idx >> 3, c = idx & 7;
        const uint32_t soff = (uint32_t)r * 128 + ((uint32_t)(c ^ (r & 7)) << 4);
        const long gg = ((long)(b * SQL + q0 + r)) * DM + h * DH + c * 8;
        CP_ASYNC16(sQh + soff, qh + gg);
        CP_ASYNC16(sQl + soff, ql + gg);
    }
    auto issue_tile = [&](int t) {
        const uint32_t bufb = sb + 32768 + (uint32_t)(t & 1) * MHA_STAGE;
        #pragma unroll
        for (int j = 0; j < 2; ++j) {
            const int idx = tid + j * 256;
            const int r = idx >> 3, c = idx & 7;
            const uint32_t soff = (uint32_t)r * 128 + ((uint32_t)(c ^ (r & 7)) << 4);
            const long gk = ((long)(b * SKL + t * 64 + r)) * DM + h * DH + c * 8;
            CP_ASYNC16(bufb + soff, kh + gk);
            const long gv = ((long)(b * DM + h * DH + r)) * (long)SKL + t * 64 + c * 8;
            CP_ASYNC16(bufb + 8192 + soff, vTh + gv);
        }
    };
    issue_tile(0);
    CP_COMMIT();

    float oacc[8][4];
    #pragma unroll
    for (int i = 0; i < 8; ++i)
        #pragma unroll
        for (int j = 0; j < 4; ++j) oacc[i][j] = 0.f;
    float mrow[2] = {-1e30f, -1e30f}, lrow[2] = {0.f, 0.f};

    const int l15 = lane & 15, lk = lane >> 4;

    for (int t = 0; t < 16; ++t) {
        if (t + 1 < 16) issue_tile(t + 1);
        CP_COMMIT();
        CP_WAIT1();
        __syncthreads();
        const uint32_t bufb = sb + 32768 + (uint32_t)(t & 1) * MHA_STAGE;

        float sc[8][4];
        #pragma unroll
        for (int i = 0; i < 8; ++i)
            #pragma unroll
            for (int j = 0; j < 4; ++j) sc[i][j] = 0.f;

        #pragma unroll
        for (int ks = 0; ks < 4; ++ks) {
            const int arow = warp * 16 + l15;
            const uint32_t ac = ((uint32_t)((ks * 2 + lk) ^ (arow & 7)) << 4)
                              + (uint32_t)arow * 128;
            uint32_t aH[4], aL[4];
            LDSM_X4(aH[0], aH[1], aH[2], aH[3], sQh + ac);
            LDSM_X4(aL[0], aL[1], aL[2], aL[3], sQl + ac);
            uint32_t bH[8][2];
            #pragma unroll
            for (int p = 0; p < 4; ++p) {
                const int br = p * 16 + l15;
                const uint32_t bc = ((uint32_t)((ks * 2 + lk) ^ (br & 7)) << 4)
                                  + (uint32_t)br * 128;
                uint32_t r0, r1, r2, r3;
                LDSM_X4(r0, r1, r2, r3, bufb + bc);
                bH[2*p][0] = r0; bH[2*p][1] = r2;
                bH[2*p+1][0] = r1; bH[2*p+1][1] = r3;
            }
            #pragma unroll
            for (int nt = 0; nt < 8; ++nt) {
                MMA16816(sc[nt], aH, bH[nt]);
                MMA16816(sc[nt], aL, bH[nt]);
            }
        }

        float mx0 = -1e30f, mx1 = -1e30f;
        #pragma unroll
        for (int nt = 0; nt < 8; ++nt) {
            #pragma unroll
            for (int j = 0; j < 4; ++j) sc[nt][j] *= 0.125f;
            mx0 = fmaxf(mx0, fmaxf(sc[nt][0], sc[nt][1]));
            mx1 = fmaxf(mx1, fmaxf(sc[nt][2], sc[nt][3]));
        }
        mx0 = fmaxf(mx0, __shfl_xor_sync(0xffffffffu, mx0, 1));
        mx0 = fmaxf(mx0, __shfl_xor_sync(0xffffffffu, mx0, 2));
        mx1 = fmaxf(mx1, __shfl_xor_sync(0xffffffffu, mx1, 1));
        mx1 = fmaxf(mx1, __shfl_xor_sync(0xffffffffu, mx1, 2));
        const float mn0 = fmaxf(mrow[0], mx0), mn1 = fmaxf(mrow[1], mx1);
        const float cor0 = __expf(mrow[0] - mn0), cor1 = __expf(mrow[1] - mn1);

        uint32_t pH[8][2];
        float rs0 = 0.f, rs1 = 0.f;
        #pragma unroll
        for (int nt = 0; nt < 8; ++nt) {
            const float p0 = __expf(sc[nt][0] - mn0);
            const float p1 = __expf(sc[nt][1] - mn0);
            const float p2 = __expf(sc[nt][2] - mn1);
            const float p3 = __expf(sc[nt][3] - mn1);
            rs0 += p0 + p1; rs1 += p2 + p3;
            pH[nt][0] = pack_h2(__float2half(p0), __float2half(p1));
            pH[nt][1] = pack_h2(__float2half(p2), __float2half(p3));
        }
        rs0 += __shfl_xor_sync(0xffffffffu, rs0, 1);
        rs0 += __shfl_xor_sync(0xffffffffu, rs0, 2);
        rs1 += __shfl_xor_sync(0xffffffffu, rs1, 1);
        rs1 += __shfl_xor_sync(0xffffffffu, rs1, 2);
        lrow[0] = lrow[0] * cor0 + rs0;
        lrow[1] = lrow[1] * cor1 + rs1;
        mrow[0] = mn0; mrow[1] = mn1;
        #pragma unroll
        for (int nt = 0; nt < 8; ++nt) {
            oacc[nt][0] *= cor0; oacc[nt][1] *= cor0;
            oacc[nt][2] *= cor1; oacc[nt][3] *= cor1;
        }

        #pragma unroll
        for (int ks = 0; ks < 4; ++ks) {
            uint32_t aPh[4] = {pH[2*ks][0], pH[2*ks][1], pH[2*ks+1][0], pH[2*ks+1][1]};
            uint32_t bVh[8][2];
            #pragma unroll
            for (int p = 0; p < 4; ++p) {
                const int br = p * 16 + l15;
                const uint32_t bc = ((uint32_t)((ks * 2 + lk) ^ (br & 7)) << 4)
                                  + (uint32_t)br * 128;
                uint32_t r0, r1, r2, r3;
                LDSM_X4(r0, r1, r2, r3, bufb + 8192 + bc);
                bVh[2*p][0] = r0; bVh[2*p][1] = r2;
                bVh[2*p+1][0] = r1; bVh[2*p+1][1] = r3;
            }
            #pragma unroll
            for (int nt = 0; nt < 8; ++nt)
                MMA16816(oacc[nt], aPh, bVh[nt]);
        }
        __syncthreads();
    }

    const int g = lane >> 2, t2 = 2 * (lane & 3);
    const float inv0 = 1.f / lrow[0], inv1 = 1.f / lrow[1];
    const long qr0 = (long)(b * SQL + q0 + warp * 16 + g);
    #pragma unroll
    for (int nt = 0; nt < 8; ++nt) {
        const int d = h * DH + nt * 8 + t2;
        float2 o0; o0.x = oacc[nt][0] * inv0; o0.y = oacc[nt][1] * inv0;
        float2 o1; o1.x = oacc[nt][2] * inv1; o1.y = oacc[nt][3] * inv1;
        *(float2*)(out + qr0 * DM + d) = o0;
        *(float2*)(out + (qr0 + 8) * DM + d) = o1;
    }
}

// ---------------- launch -----------------------------------------------------
extern "C" void kernel_launch(void* const* d_in, const int* in_sizes, int n_in,
                              void* d_out, int out_size)
{
    const float* hs   = (const float*)d_in[0];
    const float* ctx  = (const float*)d_in[1];
    const float* Wq   = (const float*)d_in[2];
    const float* bq   = (const float*)d_in[3];
    const float* Wk   = (const float*)d_in[4];
    const float* bk   = (const float*)d_in[5];
    const float* Wv   = (const float*)d_in[6];
    const float* bv   = (const float*)d_in[7];
    const float* Wobs = (const float*)d_in[8];
    const float* bobs = (const float*)d_in[9];
    const float* Wmat = (const float*)d_in[10];
    const float* bmat = (const float*)d_in[11];
    const float* lng  = (const float*)d_in[12];
    const float* lnb  = (const float*)d_in[13];
    float* out = (float*)d_out;

    float *pv, *ps, *pnq, *pnk;
    __half *hsh, *ctxh, *qh, *kh, *vTh, *ph, *gh;
    __half *Wqh, *Wkh, *Wvh, *Woh, *Wmh;
    __half *mqh, *mql, *mkh;
    cudaGetSymbolAddress((void**)&pv,   g_v);
    cudaGetSymbolAddress((void**)&ps,   g_s);
    cudaGetSymbolAddress((void**)&pnq,  g_newq);
    cudaGetSymbolAddress((void**)&pnk,  g_newk);
    cudaGetSymbolAddress((void**)&hsh,  g_hsh);
    cudaGetSymbolAddress((void**)&ctxh, g_ctxh);
    cudaGetSymbolAddress((void**)&qh,   g_qh);
    cudaGetSymbolAddress((void**)&kh,   g_kh);
    cudaGetSymbolAddress((void**)&vTh,  g_vTh);
    cudaGetSymbolAddress((void**)&ph,   g_ph);
    cudaGetSymbolAddress((void**)&gh,   g_gh);
    cudaGetSymbolAddress((void**)&Wqh,  g_Wqh);
    cudaGetSymbolAddress((void**)&Wkh,  g_Wkh);
    cudaGetSymbolAddress((void**)&Wvh,  g_Wvh);
    cudaGetSymbolAddress((void**)&Woh,  g_Woh);
    cudaGetSymbolAddress((void**)&Wmh,  g_Wmh);
    cudaGetSymbolAddress((void**)&mqh,  g_mqh);
    cudaGetSymbolAddress((void**)&mql,  g_mql);
    cudaGetSymbolAddress((void**)&mkh,  g_mkh);

    cudaFuncSetAttribute(mma_gemm, cudaFuncAttributeMaxDynamicSharedMemorySize,
                         GEMM_SMEM);
    cudaFuncSetAttribute(mma_gemm_multi, cudaFuncAttributeMaxDynamicSharedMemorySize,
                         GEMM_SMEM);
    cudaFuncSetAttribute(mma_gemm_smat, cudaFuncAttributeMaxDynamicSharedMemorySize,
                         GEMM_SMEM);
    cudaFuncSetAttribute(mha_mma_kernel, cudaFuncAttributeMaxDynamicSharedMemorySize,
                         MHA_SMEM);

    const dim3 T(256);
    const dim3 gBat(8, 8, 8);
    const long sQ = 1024L * 1024;

    // input conversions
    convert_a2<<<2368, T>>>(hs, ctx, hsh, ctxh);
    CvtW cw;
    cw.s0 = Wq;   cw.d0 = Wqh;
    cw.s1 = Wk;   cw.d1 = Wkh;
    cw.s2 = Wv;   cw.d2 = Wvh;
    cw.s3 = Wobs; cw.d3 = Woh;
    cw.s4 = Wmat; cw.d4 = Wmh;
    convert_w5<<<1480, T>>>(cw);

    // q, k, v projections in ONE launch
    Gemm3 gq;
    gq.s[0] = { hsh,  Wqh, bq, nullptr, qh };
    gq.s[1] = { ctxh, Wkh, bk, nullptr, kh };
    gq.s[2] = { ctxh, Wvh, bv, pv, nullptr };
    mma_gemm_multi<<<dim3(8, 64, 3), T, GEMM_SMEM>>>(gq);
    transconv_v<<<dim3(32, 32, 8), T>>>(pv, vTh);

    // guide S (8 batches) + mat projection in ONE launch
    mma_gemm_smat<<<dim3(8, 128, 1), T, GEMM_SMEM>>>(qh, kh, ps,
                                                     kh, Wmh, bmat, pnk);
    softmax_h<<<BB * SQL, T>>>(ps, ph);
    mma_gemm<<<gBat, T, GEMM_SMEM>>>(ph, vTh, nullptr, nullptr, gh,
                                     1024, 1.f, sQ, sQ, 0, sQ);

    // obs projection
    Gemm3 go;
    go.s[0] = { gh, Woh, bobs, pnq, nullptr };
    go.s[1] = { nullptr, nullptr, nullptr, nullptr, nullptr };
    go.s[2] = { nullptr, nullptr, nullptr, nullptr, nullptr };
    mma_gemm_multi<<<dim3(8, 64, 1), T, GEMM_SMEM>>>(go);

    // merged ReLU+LN for both streams
    relu_ln_merged<<<16384, T>>>(pnq, pnk, lng, lnb, mqh, mql, mkh);

    // tensor-core multi-head attention (2 CTA/SM)
    mha_mma_kernel<<<dim3(SQL / 128, BB * NH), T, MHA_SMEM>>>(
        mqh, mql, mkh, vTh, out);
}